// round 1
// baseline (speedup 1.0000x reference)
#include <cuda_runtime.h>
#include <cuda_bf16.h>
#include <math.h>

// Problem constants (fixed shapes)
#define BATCH 2
#define SEQT  2048
#define EMB   1024
#define NHEAD 16
#define HDIM  64
#define E3    3072            // 3*EMB
#define MROWS (BATCH*SEQT)    // 4096

// Scratch (no runtime allocation allowed)
__device__ float g_qkv[(size_t)MROWS * E3];     // 4096 x 3072
__device__ float g_att[(size_t)MROWS * EMB];    // 4096 x 1024

// ---------------------------------------------------------------------------
// SGEMM: C[M,N] = A[M,K] @ B[N,K]^T   (both A and B row-major, K contiguous)
// 128x128 block tile, BK=16, 8x8 per-thread micro-tile, 256 threads.
// All dims are multiples of the tile sizes for this problem -> no bounds checks.
// ---------------------------------------------------------------------------
#define BM 128
#define BN 128
#define BK 16

__global__ void __launch_bounds__(256) sgemm_abT(
    const float* __restrict__ A, const float* __restrict__ B,
    float* __restrict__ C, int M, int N, int K)
{
    __shared__ float As[BK][BM + 4];
    __shared__ float Bs[BK][BN + 4];

    const int tid = threadIdx.x;
    const int m0 = blockIdx.y * BM;
    const int n0 = blockIdx.x * BN;
    const int tx = tid & 15;   // n direction (16)
    const int ty = tid >> 4;   // m direction (16)

    const int lr = tid >> 2;   // 0..63 (load row base)
    const int lc = tid & 3;    // k float4 chunk 0..3

    float acc[8][8];
    #pragma unroll
    for (int i = 0; i < 8; i++)
        #pragma unroll
        for (int j = 0; j < 8; j++) acc[i][j] = 0.f;

    for (int k0 = 0; k0 < K; k0 += BK) {
        // Load A and B tiles (transposed into SMEM: [k][m])
        #pragma unroll
        for (int it = 0; it < 2; it++) {
            const int row = lr + it * 64;
            float4 va = *(const float4*)&A[(size_t)(m0 + row) * K + k0 + lc * 4];
            As[lc*4+0][row] = va.x; As[lc*4+1][row] = va.y;
            As[lc*4+2][row] = va.z; As[lc*4+3][row] = va.w;
            float4 vb = *(const float4*)&B[(size_t)(n0 + row) * K + k0 + lc * 4];
            Bs[lc*4+0][row] = vb.x; Bs[lc*4+1][row] = vb.y;
            Bs[lc*4+2][row] = vb.z; Bs[lc*4+3][row] = vb.w;
        }
        __syncthreads();

        #pragma unroll
        for (int k = 0; k < BK; k++) {
            float4 a0 = *(const float4*)&As[k][ty * 8];
            float4 a1 = *(const float4*)&As[k][ty * 8 + 4];
            float4 b0 = *(const float4*)&Bs[k][tx * 8];
            float4 b1 = *(const float4*)&Bs[k][tx * 8 + 4];
            float ar[8] = {a0.x,a0.y,a0.z,a0.w,a1.x,a1.y,a1.z,a1.w};
            float br[8] = {b0.x,b0.y,b0.z,b0.w,b1.x,b1.y,b1.z,b1.w};
            #pragma unroll
            for (int i = 0; i < 8; i++)
                #pragma unroll
                for (int j = 0; j < 8; j++)
                    acc[i][j] = fmaf(ar[i], br[j], acc[i][j]);
        }
        __syncthreads();
    }

    // Write back (float4 stores)
    #pragma unroll
    for (int i = 0; i < 8; i++) {
        float* crow = &C[(size_t)(m0 + ty * 8 + i) * N + n0 + tx * 8];
        *(float4*)(crow + 0) = make_float4(acc[i][0], acc[i][1], acc[i][2], acc[i][3]);
        *(float4*)(crow + 4) = make_float4(acc[i][4], acc[i][5], acc[i][6], acc[i][7]);
    }
}

// ---------------------------------------------------------------------------
// RoPE applied in-place to q (cols [0,1024)) and k (cols [1024,2048)) of g_qkv.
// One thread per (b,t,h,j) rotation pair, j in [0,32).
// ---------------------------------------------------------------------------
__global__ void rope_kernel(float* __restrict__ qkv)
{
    const int idx = blockIdx.x * blockDim.x + threadIdx.x;   // 2^22 total
    const int j = idx & 31;
    const int h = (idx >> 5) & 15;
    const int t = (idx >> 9) & 2047;
    const int b = idx >> 20;

    // inv_freq = 10000^(-2j/64) = 2^(-j * log2(10000)/32)
    const float inv_freq = exp2f(-(float)j * (13.287712379549449f / 32.0f));
    const float ang = (float)t * inv_freq;
    float s, c;
    sincosf(ang, &s, &c);   // precise version (large-arg reduction matters)

    float* p = qkv + ((size_t)(b * SEQT + t)) * E3 + h * HDIM + j;
    // q
    float q0 = p[0], q1 = p[32];
    p[0]  = q0 * c - q1 * s;
    p[32] = q1 * c + q0 * s;
    // k (offset +EMB)
    float k0 = p[EMB], k1 = p[EMB + 32];
    p[EMB]      = k0 * c - k1 * s;
    p[EMB + 32] = k1 * c + k0 * s;
}

// ---------------------------------------------------------------------------
// Causal flash attention, fp32. One query row per thread (128 q / block),
// K/V tiles of 32 rows staged through SMEM, online softmax.
// Heavy (late) query blocks are launched first (reverse qb mapping).
// ---------------------------------------------------------------------------
#define AQ 128
#define AK 32

__global__ void __launch_bounds__(128) attn_kernel(
    const float* __restrict__ qkv, float* __restrict__ out)
{
    const int bh = blockIdx.y;
    const int b = bh >> 4;
    const int h = bh & 15;
    const int qb = (gridDim.x - 1) - blockIdx.x;   // heavy blocks first
    const int q = qb * AQ + threadIdx.x;
    const int kend = qb * AQ + AQ;                 // exclusive key bound for block
    const float scale = 0.125f;                    // 1/sqrt(64)

    const float* base = qkv + (size_t)b * SEQT * E3 + h * HDIM;

    float qreg[64];
    {
        const float4* qp = (const float4*)(base + (size_t)q * E3);
        #pragma unroll
        for (int i = 0; i < 16; i++) {
            float4 v = qp[i];
            qreg[4*i]   = v.x; qreg[4*i+1] = v.y;
            qreg[4*i+2] = v.z; qreg[4*i+3] = v.w;
        }
    }

    __shared__ float Ks[AK][64];
    __shared__ float Vs[AK][64];

    float acc[64];
    #pragma unroll
    for (int d = 0; d < 64; d++) acc[d] = 0.f;
    float mrun = -1e30f, lrun = 0.f;

    const int tid = threadIdx.x;
    for (int kb = 0; kb < kend; kb += AK) {
        // Stage K,V tiles: 32x64 floats each = 512 float4; 4 per thread per tile
        #pragma unroll
        for (int i = 0; i < 4; i++) {
            int fi = tid + i * 128;          // 0..511
            int row = fi >> 4;
            int c4  = fi & 15;
            const float* gk = base + (size_t)(kb + row) * E3 + EMB;
            const float* gv = base + (size_t)(kb + row) * E3 + 2 * EMB;
            ((float4*)Ks[row])[c4] = ((const float4*)gk)[c4];
            ((float4*)Vs[row])[c4] = ((const float4*)gv)[c4];
        }
        __syncthreads();

        if (kb <= q) {
            float s[AK];
            float smax = -1e30f;
            #pragma unroll
            for (int j = 0; j < AK; j++) {
                float t0 = 0.f;
                #pragma unroll
                for (int d4 = 0; d4 < 16; d4++) {
                    float4 kv = ((const float4*)Ks[j])[d4];
                    t0 = fmaf(qreg[4*d4],   kv.x, t0);
                    t0 = fmaf(qreg[4*d4+1], kv.y, t0);
                    t0 = fmaf(qreg[4*d4+2], kv.z, t0);
                    t0 = fmaf(qreg[4*d4+3], kv.w, t0);
                }
                t0 *= scale;
                if (kb + j > q) t0 = -1e30f;
                s[j] = t0;
                smax = fmaxf(smax, t0);
            }
            const float mnew = fmaxf(mrun, smax);
            const float alpha = __expf(mrun - mnew);
            lrun *= alpha;
            #pragma unroll
            for (int d = 0; d < 64; d++) acc[d] *= alpha;
            #pragma unroll
            for (int j = 0; j < AK; j++) {
                const float p = __expf(s[j] - mnew);
                lrun += p;
                #pragma unroll
                for (int d4 = 0; d4 < 16; d4++) {
                    float4 vv = ((const float4*)Vs[j])[d4];
                    acc[4*d4]   = fmaf(p, vv.x, acc[4*d4]);
                    acc[4*d4+1] = fmaf(p, vv.y, acc[4*d4+1]);
                    acc[4*d4+2] = fmaf(p, vv.z, acc[4*d4+2]);
                    acc[4*d4+3] = fmaf(p, vv.w, acc[4*d4+3]);
                }
            }
            mrun = mnew;
        }
        __syncthreads();
    }

    const float inv_l = 1.0f / lrun;
    float* op = out + ((size_t)(b * SEQT + q)) * EMB + h * HDIM;
    #pragma unroll
    for (int d4 = 0; d4 < 16; d4++) {
        ((float4*)op)[d4] = make_float4(acc[4*d4] * inv_l, acc[4*d4+1] * inv_l,
                                        acc[4*d4+2] * inv_l, acc[4*d4+3] * inv_l);
    }
}

// ---------------------------------------------------------------------------
// Launch: qkv gemm -> rope -> attention -> output gemm
// ---------------------------------------------------------------------------
extern "C" void kernel_launch(void* const* d_in, const int* in_sizes, int n_in,
                              void* d_out, int out_size)
{
    const float* x  = (const float*)d_in[0];   // (B,T,E)
    const float* W1 = (const float*)d_in[1];   // (3E,E)
    const float* W2 = (const float*)d_in[2];   // (E,E)
    float* out = (float*)d_out;                // (B,T,E)

    void* p_qkv = nullptr;
    void* p_att = nullptr;
    cudaGetSymbolAddress(&p_qkv, g_qkv);
    cudaGetSymbolAddress(&p_att, g_att);
    float* qkv = (float*)p_qkv;
    float* att = (float*)p_att;

    // 1) qkv = x @ W1^T : (4096 x 3072)
    dim3 g1(E3 / BN, MROWS / BM);
    sgemm_abT<<<g1, 256>>>(x, W1, qkv, MROWS, E3, EMB);

    // 2) RoPE on q,k in place
    rope_kernel<<<(BATCH * SEQT * NHEAD * 32) / 256, 256>>>(qkv);

    // 3) causal attention -> att (4096 x 1024)
    dim3 ga(SEQT / AQ, BATCH * NHEAD);
    attn_kernel<<<ga, 128>>>(qkv, att);

    // 4) out = att @ W2^T : (4096 x 1024)
    dim3 g2(EMB / BN, MROWS / BM);
    sgemm_abT<<<g2, 256>>>(att, W2, out, MROWS, EMB, EMB);
}

// round 5
// speedup vs baseline: 3.5737x; 3.5737x over previous
#include <cuda_runtime.h>
#include <cuda_bf16.h>
#include <cuda_fp16.h>
#include <math.h>
#include <stdint.h>

// ---------------------------------------------------------------------------
// Problem constants
// ---------------------------------------------------------------------------
#define BATCH 2
#define SEQT  2048
#define EMB   1024
#define NHEAD 16
#define HDIM  64
#define E3    3072
#define MROWS (BATCH*SEQT)   // 4096
#define KDIM  1024

// ---------------------------------------------------------------------------
// Scratch (__device__ globals; no runtime allocation)
// ---------------------------------------------------------------------------
__device__ float g_qkv[(size_t)MROWS * E3];                 // fp32 qkv
__device__ __nv_bfloat16 g_xh[(size_t)MROWS * KDIM];
__device__ __nv_bfloat16 g_xl[(size_t)MROWS * KDIM];
__device__ __nv_bfloat16 g_w1h[(size_t)E3 * KDIM];
__device__ __nv_bfloat16 g_w1l[(size_t)E3 * KDIM];
__device__ __nv_bfloat16 g_w2h[(size_t)EMB * KDIM];
__device__ __nv_bfloat16 g_w2l[(size_t)EMB * KDIM];
__device__ __nv_bfloat16 g_ah[(size_t)MROWS * KDIM];        // attention out hi
__device__ __nv_bfloat16 g_al[(size_t)MROWS * KDIM];        // attention out lo
__device__ __half g_qh[(size_t)BATCH * NHEAD * SEQT * HDIM]; // fp16 q (scaled)
__device__ __half g_kh[(size_t)BATCH * NHEAD * SEQT * HDIM];
__device__ __half g_vh[(size_t)BATCH * NHEAD * SEQT * HDIM];

// ---------------------------------------------------------------------------
// Helpers: smem addr, cp.async, ldmatrix, mma
// ---------------------------------------------------------------------------
__device__ __forceinline__ uint32_t smem_u32(const void* p) {
    uint32_t a;
    asm("{ .reg .u64 t; cvta.to.shared.u64 t, %1; cvt.u32.u64 %0, t; }" : "=r"(a) : "l"(p));
    return a;
}
__device__ __forceinline__ void cp_async16(uint32_t dst, const void* src) {
    asm volatile("cp.async.cg.shared.global [%0], [%1], 16;" :: "r"(dst), "l"(src));
}
__device__ __forceinline__ void cp_commit() {
    asm volatile("cp.async.commit_group;" ::: "memory");
}
template <int N> __device__ __forceinline__ void cp_wait() {
    asm volatile("cp.async.wait_group %0;" :: "n"(N) : "memory");
}
__device__ __forceinline__ void ldsm4(uint32_t* r, uint32_t addr) {
    asm volatile("ldmatrix.sync.aligned.m8n8.x4.shared.b16 {%0,%1,%2,%3}, [%4];"
        : "=r"(r[0]), "=r"(r[1]), "=r"(r[2]), "=r"(r[3]) : "r"(addr));
}
__device__ __forceinline__ void ldsm4t(uint32_t* r, uint32_t addr) {
    asm volatile("ldmatrix.sync.aligned.m8n8.x4.trans.shared.b16 {%0,%1,%2,%3}, [%4];"
        : "=r"(r[0]), "=r"(r[1]), "=r"(r[2]), "=r"(r[3]) : "r"(addr));
}
__device__ __forceinline__ void mma_bf16(float* c, const uint32_t* a, uint32_t b0, uint32_t b1) {
    asm volatile(
        "mma.sync.aligned.m16n8k16.row.col.f32.bf16.bf16.f32 "
        "{%0,%1,%2,%3}, {%4,%5,%6,%7}, {%8,%9}, {%0,%1,%2,%3};"
        : "+f"(c[0]), "+f"(c[1]), "+f"(c[2]), "+f"(c[3])
        : "r"(a[0]), "r"(a[1]), "r"(a[2]), "r"(a[3]), "r"(b0), "r"(b1));
}
__device__ __forceinline__ void mma_f16(float* c, const uint32_t* a, uint32_t b0, uint32_t b1) {
    asm volatile(
        "mma.sync.aligned.m16n8k16.row.col.f32.f16.f16.f32 "
        "{%0,%1,%2,%3}, {%4,%5,%6,%7}, {%8,%9}, {%0,%1,%2,%3};"
        : "+f"(c[0]), "+f"(c[1]), "+f"(c[2]), "+f"(c[3])
        : "r"(a[0]), "r"(a[1]), "r"(a[2]), "r"(a[3]), "r"(b0), "r"(b1));
}

// ---------------------------------------------------------------------------
// fp32 -> (bf16 hi, bf16 lo) split
// ---------------------------------------------------------------------------
__global__ void convert_hilo(const float* __restrict__ src,
                             __nv_bfloat16* __restrict__ hi,
                             __nv_bfloat16* __restrict__ lo, int n4)
{
    int i = blockIdx.x * blockDim.x + threadIdx.x;
    if (i >= n4) return;
    float4 v = ((const float4*)src)[i];
    __nv_bfloat16 h0 = __float2bfloat16_rn(v.x);
    __nv_bfloat16 h1 = __float2bfloat16_rn(v.y);
    __nv_bfloat16 h2 = __float2bfloat16_rn(v.z);
    __nv_bfloat16 h3 = __float2bfloat16_rn(v.w);
    __nv_bfloat16 l0 = __float2bfloat16_rn(v.x - __bfloat162float(h0));
    __nv_bfloat16 l1 = __float2bfloat16_rn(v.y - __bfloat162float(h1));
    __nv_bfloat16 l2 = __float2bfloat16_rn(v.z - __bfloat162float(h2));
    __nv_bfloat16 l3 = __float2bfloat16_rn(v.w - __bfloat162float(h3));
    __nv_bfloat162* hp = (__nv_bfloat162*)hi;
    __nv_bfloat162* lp = (__nv_bfloat162*)lo;
    __nv_bfloat162 t;
    t.x = h0; t.y = h1; hp[2 * i] = t;
    t.x = h2; t.y = h3; hp[2 * i + 1] = t;
    t.x = l0; t.y = l1; lp[2 * i] = t;
    t.x = l2; t.y = l3; lp[2 * i + 1] = t;
}

// ---------------------------------------------------------------------------
// mma.sync GEMM with bf16 hi/lo 3-way compensation.
// C[M,N] = A[M,K] @ B[N,K]^T, fp32 out. 128x128x32 tiles, 256 threads (8 warps
// as 4m x 2n), 2-stage cp.async pipeline. K hardcoded = 1024.
// ---------------------------------------------------------------------------
#define GBM 128
#define GBN 128
#define GBK 32
#define GSK 40                      // padded smem stride (halves)
#define MATH (GBM * GSK)            // 5120 halves per matrix tile
#define STG_HALVES (4 * MATH)       // Ah,Al,Bh,Bl
#define GEMM_SMEM (2 * STG_HALVES * 2)  // bytes = 81920

__device__ __forceinline__ void gemm_load_stage(
    uint32_t s0, int tid, int kc, int m0, int n0,
    const __nv_bfloat16* __restrict__ Ah, const __nv_bfloat16* __restrict__ Al,
    const __nv_bfloat16* __restrict__ Bh, const __nv_bfloat16* __restrict__ Bl)
{
    const __nv_bfloat16* g0 = Ah + (size_t)m0 * KDIM + kc * GBK;
    const __nv_bfloat16* g1 = Al + (size_t)m0 * KDIM + kc * GBK;
    const __nv_bfloat16* g2 = Bh + (size_t)n0 * KDIM + kc * GBK;
    const __nv_bfloat16* g3 = Bl + (size_t)n0 * KDIM + kc * GBK;
    #pragma unroll
    for (int it = 0; it < 2; it++) {
        const int jj = tid + it * 256;        // 0..511
        const int row = jj >> 2;
        const int c = jj & 3;
        const uint32_t d = s0 + (uint32_t)(row * GSK + c * 8) * 2;
        const size_t goff = (size_t)row * KDIM + c * 8;
        cp_async16(d,                 g0 + goff);
        cp_async16(d + MATH * 2,      g1 + goff);
        cp_async16(d + 2 * MATH * 2,  g2 + goff);
        cp_async16(d + 3 * MATH * 2,  g3 + goff);
    }
    cp_commit();
}

__global__ void __launch_bounds__(256)
gemm_bf16x3(const __nv_bfloat16* __restrict__ Ah, const __nv_bfloat16* __restrict__ Al,
            const __nv_bfloat16* __restrict__ Bh, const __nv_bfloat16* __restrict__ Bl,
            float* __restrict__ C, int N)
{
    extern __shared__ char smem[];
    const uint32_t sb = smem_u32(smem);
    const int tid = threadIdx.x;
    const int wid = tid >> 5;
    const int lane = tid & 31;
    const int wm = wid >> 1;    // 0..3
    const int wn = wid & 1;     // 0..1
    const int m0 = blockIdx.y * GBM;
    const int n0 = blockIdx.x * GBN;

    float acc[2][8][4];
    #pragma unroll
    for (int i = 0; i < 2; i++)
        #pragma unroll
        for (int j = 0; j < 8; j++)
            #pragma unroll
            for (int k = 0; k < 4; k++) acc[i][j][k] = 0.f;

    gemm_load_stage(sb, tid, 0, m0, n0, Ah, Al, Bh, Bl);

    const int NCH = KDIM / GBK;   // 32
    for (int c = 0; c < NCH; c++) {
        const uint32_t scur = sb + (uint32_t)(c & 1) * STG_HALVES * 2;
        if (c + 1 < NCH) {
            gemm_load_stage(sb + (uint32_t)((c + 1) & 1) * STG_HALVES * 2,
                            tid, c + 1, m0, n0, Ah, Al, Bh, Bl);
            cp_wait<1>();
        } else {
            cp_wait<0>();
        }
        __syncthreads();

        const uint32_t sAh = scur;
        const uint32_t sAl = scur + MATH * 2;
        const uint32_t sBh = scur + 2 * MATH * 2;
        const uint32_t sBl = scur + 3 * MATH * 2;

        #pragma unroll
        for (int ks = 0; ks < 2; ks++) {
            const int k0 = ks * 16;
            uint32_t aH[2][4], aL[2][4], bH[4][4], bL[4][4];
            #pragma unroll
            for (int mi = 0; mi < 2; mi++) {
                const int row = wm * 32 + mi * 16 + (lane & 15);
                const int col = k0 + ((lane >> 4) << 3);
                const uint32_t off = (uint32_t)(row * GSK + col) * 2;
                ldsm4(aH[mi], sAh + off);
                ldsm4(aL[mi], sAl + off);
            }
            #pragma unroll
            for (int p = 0; p < 4; p++) {
                const int row = wn * 64 + p * 16 + (lane & 7) + ((lane >> 4) << 3);
                const int col = k0 + (((lane >> 3) & 1) << 3);
                const uint32_t off = (uint32_t)(row * GSK + col) * 2;
                ldsm4(bH[p], sBh + off);
                ldsm4(bL[p], sBl + off);
            }
            #pragma unroll
            for (int mi = 0; mi < 2; mi++) {
                #pragma unroll
                for (int p = 0; p < 4; p++) {
                    mma_bf16(acc[mi][2 * p],     aH[mi], bH[p][0], bH[p][1]);
                    mma_bf16(acc[mi][2 * p + 1], aH[mi], bH[p][2], bH[p][3]);
                    mma_bf16(acc[mi][2 * p],     aL[mi], bH[p][0], bH[p][1]);
                    mma_bf16(acc[mi][2 * p + 1], aL[mi], bH[p][2], bH[p][3]);
                    mma_bf16(acc[mi][2 * p],     aH[mi], bL[p][0], bL[p][1]);
                    mma_bf16(acc[mi][2 * p + 1], aH[mi], bL[p][2], bL[p][3]);
                }
            }
        }
        __syncthreads();
    }

    // Epilogue
    #pragma unroll
    for (int mi = 0; mi < 2; mi++) {
        const int r0 = m0 + wm * 32 + mi * 16 + (lane >> 2);
        #pragma unroll
        for (int nj = 0; nj < 8; nj++) {
            const int col = n0 + wn * 64 + nj * 8 + 2 * (lane & 3);
            *(float2*)&C[(size_t)r0 * N + col] = make_float2(acc[mi][nj][0], acc[mi][nj][1]);
            *(float2*)&C[(size_t)(r0 + 8) * N + col] = make_float2(acc[mi][nj][2], acc[mi][nj][3]);
        }
    }
}

// ---------------------------------------------------------------------------
// RoPE + repack to fp16 [b][h][t][d], 1/8 score scale folded into q.
// ---------------------------------------------------------------------------
__global__ void rope_repack(const float* __restrict__ qkv,
                            __half* __restrict__ qh, __half* __restrict__ kh,
                            __half* __restrict__ vh)
{
    const int idx = blockIdx.x * blockDim.x + threadIdx.x;
    const int j = idx & 31;
    const int h = (idx >> 5) & 15;
    const int t = (idx >> 9) & 2047;
    const int b = idx >> 20;

    const float inv_freq = exp2f(-(float)j * (13.287712379549449f / 32.0f));
    float s, c;
    sincosf((float)t * inv_freq, &s, &c);

    const float* p = qkv + ((size_t)(b * SEQT + t)) * E3 + h * HDIM + j;
    const float q0 = p[0], q1 = p[32];
    const float k0 = p[EMB], k1 = p[EMB + 32];
    const float v0 = p[2 * EMB], v1 = p[2 * EMB + 32];

    const size_t o = ((size_t)((b * NHEAD + h) * SEQT + t)) * HDIM + j;
    qh[o]      = __float2half(0.125f * (q0 * c - q1 * s));
    qh[o + 32] = __float2half(0.125f * (q1 * c + q0 * s));
    kh[o]      = __float2half(k0 * c - k1 * s);
    kh[o + 32] = __float2half(k1 * c + k0 * s);
    vh[o]      = __float2half(v0);
    vh[o + 32] = __float2half(v1);
}

// ---------------------------------------------------------------------------
// fp16 mma.sync causal flash attention.
// Block: 128 threads (4 warps), 64 queries (warp = m16). K-tile = 64.
// Double-buffered cp.async K/V. Output: bf16 hi/lo into [b][t][h*64+d].
// ---------------------------------------------------------------------------
#define SV 72   // smem row stride (halves)

__global__ void __launch_bounds__(128) attn_mma(
    const __half* __restrict__ qh, const __half* __restrict__ kh,
    const __half* __restrict__ vh,
    __nv_bfloat16* __restrict__ outh, __nv_bfloat16* __restrict__ outl)
{
    __shared__ __half Qs[64 * SV];
    __shared__ __half Ks[2][64 * SV];
    __shared__ __half Vs[2][64 * SV];

    const int bh = blockIdx.y;
    const int b = bh >> 4;
    const int h = bh & 15;
    const int qt = (gridDim.x - 1) - blockIdx.x;   // heavy tiles first
    const int tid = threadIdx.x;
    const int wid = tid >> 5;
    const int lane = tid & 31;

    const __half* qg = qh + (size_t)bh * SEQT * HDIM;
    const __half* kg = kh + (size_t)bh * SEQT * HDIM;
    const __half* vg = vh + (size_t)bh * SEQT * HDIM;

    const uint32_t sQ = smem_u32(Qs);
    const uint32_t sK0 = smem_u32(Ks[0]);
    const uint32_t sV0 = smem_u32(Vs[0]);

    // Load Q tile: 64 rows x 64 halves = 512 16B chunks (8 chunks/row), 4/thread
    #pragma unroll
    for (int i = 0; i < 4; i++) {
        const int ch = tid + i * 128;
        const int row = ch >> 3;
        const int c = ch & 7;
        cp_async16(sQ + (uint32_t)(row * SV + c * 8) * 2,
                   qg + (size_t)(qt * 64 + row) * HDIM + c * 8);
    }
    cp_commit();

    // Prefetch K/V tile 0 (512 chunks each)
    {
        #pragma unroll
        for (int i = 0; i < 4; i++) {
            const int ch = tid + i * 128;
            const int row = ch >> 3;
            const int c = ch & 7;
            const uint32_t d = (uint32_t)(row * SV + c * 8) * 2;
            const size_t goff = (size_t)row * HDIM + c * 8;
            cp_async16(sK0 + d, kg + goff);
            cp_async16(sV0 + d, vg + goff);
        }
        cp_commit();
    }

    cp_wait<1>();   // Q ready
    __syncthreads();

    // Q fragments: 4 k-steps
    uint32_t aq[4][4];
    #pragma unroll
    for (int ks = 0; ks < 4; ks++) {
        const int row = wid * 16 + (lane & 15);
        const int col = ks * 16 + ((lane >> 4) << 3);
        ldsm4(aq[ks], sQ + (uint32_t)(row * SV + col) * 2);
    }

    float o[8][4];
    #pragma unroll
    for (int j = 0; j < 8; j++)
        #pragma unroll
        for (int k = 0; k < 4; k++) o[j][k] = 0.f;
    float mr[2] = {-1e30f, -1e30f};
    float lr[2] = {0.f, 0.f};

    for (int kt = 0; kt <= qt; kt++) {
        const int cb = kt & 1;
        if (kt < qt) {
            const uint32_t sKn = smem_u32(Ks[1 - cb]);
            const uint32_t sVn = smem_u32(Vs[1 - cb]);
            #pragma unroll
            for (int i = 0; i < 4; i++) {
                const int ch = tid + i * 128;
                const int row = ch >> 3;
                const int c = ch & 7;
                const uint32_t d = (uint32_t)(row * SV + c * 8) * 2;
                const size_t goff = (size_t)((kt + 1) * 64 + row) * HDIM + c * 8;
                cp_async16(sKn + d, kg + goff);
                cp_async16(sVn + d, vg + goff);
            }
            cp_commit();
            cp_wait<1>();
        } else {
            cp_wait<0>();
        }
        __syncthreads();

        const uint32_t sK = smem_u32(Ks[cb]);
        const uint32_t sV = smem_u32(Vs[cb]);

        // ---- S = Q K^T ----
        float sacc[8][4];
        #pragma unroll
        for (int j = 0; j < 8; j++)
            #pragma unroll
            for (int k = 0; k < 4; k++) sacc[j][k] = 0.f;

        #pragma unroll
        for (int ks = 0; ks < 4; ks++) {
            uint32_t bk[4][4];
            #pragma unroll
            for (int p = 0; p < 4; p++) {
                const int row = p * 16 + (lane & 7) + ((lane >> 4) << 3);
                const int col = ks * 16 + (((lane >> 3) & 1) << 3);
                ldsm4(bk[p], sK + (uint32_t)(row * SV + col) * 2);
            }
            #pragma unroll
            for (int p = 0; p < 4; p++) {
                mma_f16(sacc[2 * p],     aq[ks], bk[p][0], bk[p][1]);
                mma_f16(sacc[2 * p + 1], aq[ks], bk[p][2], bk[p][3]);
            }
        }

        // ---- causal mask (diagonal tile only) ----
        if (kt == qt) {
            const int qlocal = wid * 16 + (lane >> 2);
            #pragma unroll
            for (int nj = 0; nj < 8; nj++) {
                const int col = nj * 8 + 2 * (lane & 3);
                if (col > qlocal)         sacc[nj][0] = -1e30f;
                if (col + 1 > qlocal)     sacc[nj][1] = -1e30f;
                if (col > qlocal + 8)     sacc[nj][2] = -1e30f;
                if (col + 1 > qlocal + 8) sacc[nj][3] = -1e30f;
            }
        }

        // ---- online softmax (rows r=0: c0,c1 ; r=1: c2,c3) ----
        #pragma unroll
        for (int r = 0; r < 2; r++) {
            float mt = -1e30f;
            #pragma unroll
            for (int nj = 0; nj < 8; nj++)
                mt = fmaxf(mt, fmaxf(sacc[nj][2 * r], sacc[nj][2 * r + 1]));
            mt = fmaxf(mt, __shfl_xor_sync(0xFFFFFFFFu, mt, 1));
            mt = fmaxf(mt, __shfl_xor_sync(0xFFFFFFFFu, mt, 2));
            const float mnew = fmaxf(mr[r], mt);
            const float alpha = __expf(mr[r] - mnew);
            mr[r] = mnew;
            lr[r] *= alpha;
            #pragma unroll
            for (int nj = 0; nj < 8; nj++) {
                o[nj][2 * r] *= alpha;
                o[nj][2 * r + 1] *= alpha;
            }
            float psum = 0.f;
            #pragma unroll
            for (int nj = 0; nj < 8; nj++) {
                const float p0 = __expf(sacc[nj][2 * r] - mnew);
                const float p1 = __expf(sacc[nj][2 * r + 1] - mnew);
                sacc[nj][2 * r] = p0;
                sacc[nj][2 * r + 1] = p1;
                psum += p0 + p1;
            }
            lr[r] += psum;
        }

        // ---- P fragments (fp16): accumulator layout -> A fragment layout ----
        uint32_t ap[4][4];
        #pragma unroll
        for (int kp = 0; kp < 4; kp++) {
            const int nj = 2 * kp;
            __half2 t0 = __float22half2_rn(make_float2(sacc[nj][0], sacc[nj][1]));
            __half2 t1 = __float22half2_rn(make_float2(sacc[nj][2], sacc[nj][3]));
            __half2 t2 = __float22half2_rn(make_float2(sacc[nj + 1][0], sacc[nj + 1][1]));
            __half2 t3 = __float22half2_rn(make_float2(sacc[nj + 1][2], sacc[nj + 1][3]));
            ap[kp][0] = *(uint32_t*)&t0;
            ap[kp][1] = *(uint32_t*)&t1;
            ap[kp][2] = *(uint32_t*)&t2;
            ap[kp][3] = *(uint32_t*)&t3;
        }

        // ---- O += P V ----
        // trans-ldmatrix register order: r0=(k0-7,n0-7) r1=(k0-7,n8-15)
        //                                r2=(k8-15,n0-7) r3=(k8-15,n8-15)
        // => n-tile0 uses (r0,r2); n-tile1 uses (r1,r3)
        #pragma unroll
        for (int kp = 0; kp < 4; kp++) {
            uint32_t bv[4][4];
            #pragma unroll
            for (int pd = 0; pd < 4; pd++) {
                const int row = kp * 16 + (lane & 7) + ((lane >> 4) << 3);
                const int col = pd * 16 + (((lane >> 3) & 1) << 3);
                ldsm4t(bv[pd], sV + (uint32_t)(row * SV + col) * 2);
            }
            #pragma unroll
            for (int pd = 0; pd < 4; pd++) {
                mma_f16(o[2 * pd],     ap[kp], bv[pd][0], bv[pd][2]);
                mma_f16(o[2 * pd + 1], ap[kp], bv[pd][1], bv[pd][3]);
            }
        }
        __syncthreads();
    }

    // ---- epilogue: normalize + bf16 hi/lo ----
    float inv[2];
    #pragma unroll
    for (int r = 0; r < 2; r++) {
        float ls = lr[r];
        ls += __shfl_xor_sync(0xFFFFFFFFu, ls, 1);
        ls += __shfl_xor_sync(0xFFFFFFFFu, ls, 2);
        inv[r] = 1.0f / ls;
    }
    #pragma unroll
    for (int r = 0; r < 2; r++) {
        const int trow = qt * 64 + wid * 16 + (lane >> 2) + 8 * r;
        const size_t rowoff = (size_t)(b * SEQT + trow) * EMB + h * HDIM;
        #pragma unroll
        for (int nj = 0; nj < 8; nj++) {
            const int col = nj * 8 + 2 * (lane & 3);
            const float v0 = o[nj][2 * r] * inv[r];
            const float v1 = o[nj][2 * r + 1] * inv[r];
            const __nv_bfloat16 h0 = __float2bfloat16_rn(v0);
            const __nv_bfloat16 h1 = __float2bfloat16_rn(v1);
            const __nv_bfloat16 l0 = __float2bfloat16_rn(v0 - __bfloat162float(h0));
            const __nv_bfloat16 l1 = __float2bfloat16_rn(v1 - __bfloat162float(h1));
            __nv_bfloat162 ph; ph.x = h0; ph.y = h1;
            __nv_bfloat162 pl; pl.x = l0; pl.y = l1;
            *(__nv_bfloat162*)&outh[rowoff + col] = ph;
            *(__nv_bfloat162*)&outl[rowoff + col] = pl;
        }
    }
}

// ---------------------------------------------------------------------------
// Launch sequence
// ---------------------------------------------------------------------------
extern "C" void kernel_launch(void* const* d_in, const int* in_sizes, int n_in,
                              void* d_out, int out_size)
{
    const float* x  = (const float*)d_in[0];
    const float* W1 = (const float*)d_in[1];
    const float* W2 = (const float*)d_in[2];
    float* out = (float*)d_out;

    void *p_qkv, *p_xh, *p_xl, *p_w1h, *p_w1l, *p_w2h, *p_w2l, *p_ah, *p_al,
         *p_qh, *p_kh, *p_vh;
    cudaGetSymbolAddress(&p_qkv, g_qkv);
    cudaGetSymbolAddress(&p_xh, g_xh);   cudaGetSymbolAddress(&p_xl, g_xl);
    cudaGetSymbolAddress(&p_w1h, g_w1h); cudaGetSymbolAddress(&p_w1l, g_w1l);
    cudaGetSymbolAddress(&p_w2h, g_w2h); cudaGetSymbolAddress(&p_w2l, g_w2l);
    cudaGetSymbolAddress(&p_ah, g_ah);   cudaGetSymbolAddress(&p_al, g_al);
    cudaGetSymbolAddress(&p_qh, g_qh);   cudaGetSymbolAddress(&p_kh, g_kh);
    cudaGetSymbolAddress(&p_vh, g_vh);

    cudaFuncSetAttribute(gemm_bf16x3, cudaFuncAttributeMaxDynamicSharedMemorySize, GEMM_SMEM);

    // hi/lo conversions of inputs
    convert_hilo<<<(MROWS * KDIM / 4 + 255) / 256, 256>>>(
        x, (__nv_bfloat16*)p_xh, (__nv_bfloat16*)p_xl, MROWS * KDIM / 4);
    convert_hilo<<<(E3 * KDIM / 4 + 255) / 256, 256>>>(
        W1, (__nv_bfloat16*)p_w1h, (__nv_bfloat16*)p_w1l, E3 * KDIM / 4);
    convert_hilo<<<(EMB * KDIM / 4 + 255) / 256, 256>>>(
        W2, (__nv_bfloat16*)p_w2h, (__nv_bfloat16*)p_w2l, EMB * KDIM / 4);

    // qkv = x @ W1^T
    {
        dim3 g(E3 / GBN, MROWS / GBM);
        gemm_bf16x3<<<g, 256, GEMM_SMEM>>>((__nv_bfloat16*)p_xh, (__nv_bfloat16*)p_xl,
                                           (__nv_bfloat16*)p_w1h, (__nv_bfloat16*)p_w1l,
                                           (float*)p_qkv, E3);
    }

    // RoPE + fp16 repack
    rope_repack<<<(BATCH * SEQT * NHEAD * 32) / 256, 256>>>(
        (const float*)p_qkv, (__half*)p_qh, (__half*)p_kh, (__half*)p_vh);

    // attention -> bf16 hi/lo
    {
        dim3 ga(SEQT / 64, BATCH * NHEAD);
        attn_mma<<<ga, 128>>>((const __half*)p_qh, (const __half*)p_kh,
                              (const __half*)p_vh,
                              (__nv_bfloat16*)p_ah, (__nv_bfloat16*)p_al);
    }

    // out = att @ W2^T
    {
        dim3 g(EMB / GBN, MROWS / GBM);
        gemm_bf16x3<<<g, 256, GEMM_SMEM>>>((__nv_bfloat16*)p_ah, (__nv_bfloat16*)p_al,
                                           (__nv_bfloat16*)p_w2h, (__nv_bfloat16*)p_w2l,
                                           out, EMB);
    }
}

// round 6
// speedup vs baseline: 5.7960x; 1.6219x over previous
#include <cuda_runtime.h>
#include <cuda_bf16.h>
#include <cuda_fp16.h>
#include <math.h>
#include <stdint.h>

// ---------------------------------------------------------------------------
// Problem constants
// ---------------------------------------------------------------------------
#define BATCH 2
#define SEQT  2048
#define EMB   1024
#define NHEAD 16
#define HDIM  64
#define E3    3072
#define MROWS (BATCH*SEQT)   // 4096
#define KDIM  1024

// ---------------------------------------------------------------------------
// Scratch (__device__ globals; no runtime allocation)
// ---------------------------------------------------------------------------
__device__ __half g_qkv[(size_t)MROWS * E3];                 // fp16 qkv
__device__ __half g_xh[(size_t)MROWS * KDIM];                // x hi
__device__ __half g_xl[(size_t)MROWS * KDIM];                // x lo
__device__ __half g_w1[(size_t)E3 * KDIM];                   // W1 fp16
__device__ __half g_w2[(size_t)EMB * KDIM];                  // W2 fp16
__device__ __half g_ah[(size_t)MROWS * KDIM];                // attn out hi
__device__ __half g_al[(size_t)MROWS * KDIM];                // attn out lo
__device__ __half g_qh[(size_t)BATCH * NHEAD * SEQT * HDIM]; // q (scaled, rope)
__device__ __half g_kh[(size_t)BATCH * NHEAD * SEQT * HDIM]; // k (rope)
__device__ __half g_vh[(size_t)BATCH * NHEAD * SEQT * HDIM]; // v

// ---------------------------------------------------------------------------
// Helpers
// ---------------------------------------------------------------------------
__device__ __forceinline__ uint32_t smem_u32(const void* p) {
    uint32_t a;
    asm("{ .reg .u64 t; cvta.to.shared.u64 t, %1; cvt.u32.u64 %0, t; }" : "=r"(a) : "l"(p));
    return a;
}
__device__ __forceinline__ void cp_async16(uint32_t dst, const void* src) {
    asm volatile("cp.async.cg.shared.global [%0], [%1], 16;" :: "r"(dst), "l"(src));
}
__device__ __forceinline__ void cp_commit() {
    asm volatile("cp.async.commit_group;" ::: "memory");
}
template <int N> __device__ __forceinline__ void cp_wait() {
    asm volatile("cp.async.wait_group %0;" :: "n"(N) : "memory");
}
__device__ __forceinline__ void ldsm4(uint32_t* r, uint32_t addr) {
    asm volatile("ldmatrix.sync.aligned.m8n8.x4.shared.b16 {%0,%1,%2,%3}, [%4];"
        : "=r"(r[0]), "=r"(r[1]), "=r"(r[2]), "=r"(r[3]) : "r"(addr));
}
__device__ __forceinline__ void ldsm4t(uint32_t* r, uint32_t addr) {
    asm volatile("ldmatrix.sync.aligned.m8n8.x4.trans.shared.b16 {%0,%1,%2,%3}, [%4];"
        : "=r"(r[0]), "=r"(r[1]), "=r"(r[2]), "=r"(r[3]) : "r"(addr));
}
__device__ __forceinline__ void mma_f16(float* c, const uint32_t* a, uint32_t b0, uint32_t b1) {
    asm volatile(
        "mma.sync.aligned.m16n8k16.row.col.f32.f16.f16.f32 "
        "{%0,%1,%2,%3}, {%4,%5,%6,%7}, {%8,%9}, {%0,%1,%2,%3};"
        : "+f"(c[0]), "+f"(c[1]), "+f"(c[2]), "+f"(c[3])
        : "r"(a[0]), "r"(a[1]), "r"(a[2]), "r"(a[3]), "r"(b0), "r"(b1));
}

// ---------------------------------------------------------------------------
// fp32 -> (fp16 hi, fp16 lo) split
// ---------------------------------------------------------------------------
__global__ void convert_hilo_f16(const float* __restrict__ src,
                                 __half* __restrict__ hi,
                                 __half* __restrict__ lo, int n4)
{
    int i = blockIdx.x * blockDim.x + threadIdx.x;
    if (i >= n4) return;
    float4 v = ((const float4*)src)[i];
    __half h0 = __float2half_rn(v.x);
    __half h1 = __float2half_rn(v.y);
    __half h2 = __float2half_rn(v.z);
    __half h3 = __float2half_rn(v.w);
    __half l0 = __float2half_rn(v.x - __half2float(h0));
    __half l1 = __float2half_rn(v.y - __half2float(h1));
    __half l2 = __float2half_rn(v.z - __half2float(h2));
    __half l3 = __float2half_rn(v.w - __half2float(h3));
    __half2* hp = (__half2*)hi;
    __half2* lp = (__half2*)lo;
    __half2 t;
    t.x = h0; t.y = h1; hp[2 * i] = t;
    t.x = h2; t.y = h3; hp[2 * i + 1] = t;
    t.x = l0; t.y = l1; lp[2 * i] = t;
    t.x = l2; t.y = l3; lp[2 * i + 1] = t;
}

// fp32 -> fp16 plain
__global__ void convert_f16(const float* __restrict__ src,
                            __half* __restrict__ dst, int n4)
{
    int i = blockIdx.x * blockDim.x + threadIdx.x;
    if (i >= n4) return;
    float4 v = ((const float4*)src)[i];
    __half2* dp = (__half2*)dst;
    dp[2 * i]     = __floats2half2_rn(v.x, v.y);
    dp[2 * i + 1] = __floats2half2_rn(v.z, v.w);
}

// ---------------------------------------------------------------------------
// fp16 GEMM with A hi/lo 2-MMA compensation.
// C[M,N] = (Ah+Al)[M,K] @ B[N,K]^T. 128x128x32 tiles, 256 threads (8 warps
// 4m x 2n), 3-stage cp.async ring, 2 CTAs/SM.
// ---------------------------------------------------------------------------
#define GBM 128
#define GBN 128
#define GBK 32
#define GSK 40                        // padded smem stride (halves)
#define GMAT (GBM * GSK)              // 5120 halves per matrix tile
#define GSTAGE_B (3 * GMAT * 2)       // 30720 bytes per stage (Ah,Al,B)
#define GEMM_SMEM (3 * GSTAGE_B)      // 92160 bytes

__device__ __forceinline__ void g2_load(
    uint32_t s0, int tid, int kc, int m0, int n0,
    const __half* __restrict__ Ah, const __half* __restrict__ Al,
    const __half* __restrict__ B)
{
    const __half* a0 = Ah + (size_t)m0 * KDIM + kc * GBK;
    const __half* a1 = Al + (size_t)m0 * KDIM + kc * GBK;
    const __half* b0 = B  + (size_t)n0 * KDIM + kc * GBK;
    #pragma unroll
    for (int it = 0; it < 2; it++) {
        const int jj = tid + it * 256;      // 0..511
        const int row = jj >> 2;
        const int c = jj & 3;
        const uint32_t d = s0 + (uint32_t)(row * GSK + c * 8) * 2;
        const size_t goff = (size_t)row * KDIM + c * 8;
        cp_async16(d,                 a0 + goff);
        cp_async16(d + GMAT * 2,      a1 + goff);
        cp_async16(d + 2 * GMAT * 2,  b0 + goff);
    }
    cp_commit();
}

template <bool HALF_OUT>
__global__ void __launch_bounds__(256, 2)
gemm_f16x2(const __half* __restrict__ Ah, const __half* __restrict__ Al,
           const __half* __restrict__ B, void* __restrict__ Cv, int N)
{
    extern __shared__ char smem[];
    const uint32_t sb = smem_u32(smem);
    const int tid = threadIdx.x;
    const int wid = tid >> 5;
    const int lane = tid & 31;
    const int wm = wid >> 1;    // 0..3
    const int wn = wid & 1;     // 0..1
    const int m0 = blockIdx.y * GBM;
    const int n0 = blockIdx.x * GBN;

    float acc[2][8][4];
    #pragma unroll
    for (int i = 0; i < 2; i++)
        #pragma unroll
        for (int j = 0; j < 8; j++)
            #pragma unroll
            for (int k = 0; k < 4; k++) acc[i][j][k] = 0.f;

    // prologue: stages 0, 1
    g2_load(sb,            tid, 0, m0, n0, Ah, Al, B);
    g2_load(sb + GSTAGE_B, tid, 1, m0, n0, Ah, Al, B);

    const int NCH = KDIM / GBK;   // 32
    for (int c = 0; c < NCH; c++) {
        if (c + 1 < NCH) cp_wait<1>(); else cp_wait<0>();
        __syncthreads();

        const uint32_t scur = sb + (uint32_t)(c % 3) * GSTAGE_B;
        const uint32_t sAh = scur;
        const uint32_t sAl = scur + GMAT * 2;
        const uint32_t sB  = scur + 2 * GMAT * 2;

        #pragma unroll
        for (int ks = 0; ks < 2; ks++) {
            const int k0 = ks * 16;
            uint32_t aH[2][4], aL[2][4];
            #pragma unroll
            for (int mi = 0; mi < 2; mi++) {
                const int row = wm * 32 + mi * 16 + (lane & 15);
                const int col = k0 + ((lane >> 4) << 3);
                const uint32_t off = (uint32_t)(row * GSK + col) * 2;
                ldsm4(aH[mi], sAh + off);
                ldsm4(aL[mi], sAl + off);
            }
            #pragma unroll
            for (int p = 0; p < 4; p++) {
                uint32_t bb[4];
                const int row = wn * 64 + p * 16 + (lane & 7) + ((lane >> 4) << 3);
                const int col = k0 + (((lane >> 3) & 1) << 3);
                ldsm4(bb, sB + (uint32_t)(row * GSK + col) * 2);
                #pragma unroll
                for (int mi = 0; mi < 2; mi++) {
                    mma_f16(acc[mi][2 * p],     aH[mi], bb[0], bb[1]);
                    mma_f16(acc[mi][2 * p + 1], aH[mi], bb[2], bb[3]);
                    mma_f16(acc[mi][2 * p],     aL[mi], bb[0], bb[1]);
                    mma_f16(acc[mi][2 * p + 1], aL[mi], bb[2], bb[3]);
                }
            }
        }
        // issue next-next stage AFTER compute (ring buffer freed at last sync)
        if (c + 2 < NCH)
            g2_load(sb + (uint32_t)((c + 2) % 3) * GSTAGE_B, tid, c + 2, m0, n0, Ah, Al, B);
    }

    // Epilogue
    #pragma unroll
    for (int mi = 0; mi < 2; mi++) {
        const int r0 = m0 + wm * 32 + mi * 16 + (lane >> 2);
        #pragma unroll
        for (int nj = 0; nj < 8; nj++) {
            const int col = n0 + wn * 64 + nj * 8 + 2 * (lane & 3);
            if (HALF_OUT) {
                __half* C = (__half*)Cv;
                *(__half2*)&C[(size_t)r0 * N + col] =
                    __floats2half2_rn(acc[mi][nj][0], acc[mi][nj][1]);
                *(__half2*)&C[(size_t)(r0 + 8) * N + col] =
                    __floats2half2_rn(acc[mi][nj][2], acc[mi][nj][3]);
            } else {
                float* C = (float*)Cv;
                *(float2*)&C[(size_t)r0 * N + col] = make_float2(acc[mi][nj][0], acc[mi][nj][1]);
                *(float2*)&C[(size_t)(r0 + 8) * N + col] = make_float2(acc[mi][nj][2], acc[mi][nj][3]);
            }
        }
    }
}

// ---------------------------------------------------------------------------
// RoPE + repack fp16 qkv -> fp16 [b][h][t][d], 1/8 scale folded into q.
// ---------------------------------------------------------------------------
__global__ void rope_repack(const __half* __restrict__ qkv,
                            __half* __restrict__ qh, __half* __restrict__ kh,
                            __half* __restrict__ vh)
{
    const int idx = blockIdx.x * blockDim.x + threadIdx.x;
    const int j = idx & 31;
    const int h = (idx >> 5) & 15;
    const int t = (idx >> 9) & 2047;
    const int b = idx >> 20;

    const float inv_freq = exp2f(-(float)j * (13.287712379549449f / 32.0f));
    float s, c;
    sincosf((float)t * inv_freq, &s, &c);

    const __half* p = qkv + ((size_t)(b * SEQT + t)) * E3 + h * HDIM + j;
    const float q0 = __half2float(p[0]),       q1 = __half2float(p[32]);
    const float k0 = __half2float(p[EMB]),     k1 = __half2float(p[EMB + 32]);
    const float v0 = __half2float(p[2 * EMB]), v1 = __half2float(p[2 * EMB + 32]);

    const size_t o = ((size_t)((b * NHEAD + h) * SEQT + t)) * HDIM + j;
    qh[o]      = __float2half(0.125f * (q0 * c - q1 * s));
    qh[o + 32] = __float2half(0.125f * (q1 * c + q0 * s));
    kh[o]      = __float2half(k0 * c - k1 * s);
    kh[o + 32] = __float2half(k1 * c + k0 * s);
    vh[o]      = __float2half(v0);
    vh[o + 32] = __float2half(v1);
}

// ---------------------------------------------------------------------------
// fp16 mma.sync causal flash attention. 128 threads / 64 queries; K-tile 64;
// double-buffered cp.async; output fp16 hi/lo into [b][t][h*64+d].
// ---------------------------------------------------------------------------
#define SV 72   // smem row stride (halves)

__global__ void __launch_bounds__(128) attn_mma(
    const __half* __restrict__ qh, const __half* __restrict__ kh,
    const __half* __restrict__ vh,
    __half* __restrict__ outh, __half* __restrict__ outl)
{
    __shared__ __half Qs[64 * SV];
    __shared__ __half Ks[2][64 * SV];
    __shared__ __half Vs[2][64 * SV];

    const int bh = blockIdx.y;
    const int b = bh >> 4;
    const int h = bh & 15;
    const int qt = (gridDim.x - 1) - blockIdx.x;   // heavy tiles first
    const int tid = threadIdx.x;
    const int wid = tid >> 5;
    const int lane = tid & 31;

    const __half* qg = qh + (size_t)bh * SEQT * HDIM;
    const __half* kg = kh + (size_t)bh * SEQT * HDIM;
    const __half* vg = vh + (size_t)bh * SEQT * HDIM;

    const uint32_t sQ = smem_u32(Qs);
    const uint32_t sK0 = smem_u32(Ks[0]);
    const uint32_t sV0 = smem_u32(Vs[0]);

    // Load Q tile: 64 rows x 8 chunks
    #pragma unroll
    for (int i = 0; i < 4; i++) {
        const int ch = tid + i * 128;
        const int row = ch >> 3;
        const int c = ch & 7;
        cp_async16(sQ + (uint32_t)(row * SV + c * 8) * 2,
                   qg + (size_t)(qt * 64 + row) * HDIM + c * 8);
    }
    cp_commit();

    // Prefetch K/V tile 0
    {
        #pragma unroll
        for (int i = 0; i < 4; i++) {
            const int ch = tid + i * 128;
            const int row = ch >> 3;
            const int c = ch & 7;
            const uint32_t d = (uint32_t)(row * SV + c * 8) * 2;
            const size_t goff = (size_t)row * HDIM + c * 8;
            cp_async16(sK0 + d, kg + goff);
            cp_async16(sV0 + d, vg + goff);
        }
        cp_commit();
    }

    cp_wait<1>();   // Q ready
    __syncthreads();

    uint32_t aq[4][4];
    #pragma unroll
    for (int ks = 0; ks < 4; ks++) {
        const int row = wid * 16 + (lane & 15);
        const int col = ks * 16 + ((lane >> 4) << 3);
        ldsm4(aq[ks], sQ + (uint32_t)(row * SV + col) * 2);
    }

    float o[8][4];
    #pragma unroll
    for (int j = 0; j < 8; j++)
        #pragma unroll
        for (int k = 0; k < 4; k++) o[j][k] = 0.f;
    float mr[2] = {-1e30f, -1e30f};
    float lr[2] = {0.f, 0.f};

    for (int kt = 0; kt <= qt; kt++) {
        const int cb = kt & 1;
        if (kt < qt) {
            const uint32_t sKn = smem_u32(Ks[1 - cb]);
            const uint32_t sVn = smem_u32(Vs[1 - cb]);
            #pragma unroll
            for (int i = 0; i < 4; i++) {
                const int ch = tid + i * 128;
                const int row = ch >> 3;
                const int c = ch & 7;
                const uint32_t d = (uint32_t)(row * SV + c * 8) * 2;
                const size_t goff = (size_t)((kt + 1) * 64 + row) * HDIM + c * 8;
                cp_async16(sKn + d, kg + goff);
                cp_async16(sVn + d, vg + goff);
            }
            cp_commit();
            cp_wait<1>();
        } else {
            cp_wait<0>();
        }
        __syncthreads();

        const uint32_t sK = smem_u32(Ks[cb]);
        const uint32_t sV = smem_u32(Vs[cb]);

        // ---- S = Q K^T ----
        float sacc[8][4];
        #pragma unroll
        for (int j = 0; j < 8; j++)
            #pragma unroll
            for (int k = 0; k < 4; k++) sacc[j][k] = 0.f;

        #pragma unroll
        for (int ks = 0; ks < 4; ks++) {
            uint32_t bk[4][4];
            #pragma unroll
            for (int p = 0; p < 4; p++) {
                const int row = p * 16 + (lane & 7) + ((lane >> 4) << 3);
                const int col = ks * 16 + (((lane >> 3) & 1) << 3);
                ldsm4(bk[p], sK + (uint32_t)(row * SV + col) * 2);
            }
            #pragma unroll
            for (int p = 0; p < 4; p++) {
                mma_f16(sacc[2 * p],     aq[ks], bk[p][0], bk[p][1]);
                mma_f16(sacc[2 * p + 1], aq[ks], bk[p][2], bk[p][3]);
            }
        }

        // ---- causal mask (diagonal tile only) ----
        if (kt == qt) {
            const int qlocal = wid * 16 + (lane >> 2);
            #pragma unroll
            for (int nj = 0; nj < 8; nj++) {
                const int col = nj * 8 + 2 * (lane & 3);
                if (col > qlocal)         sacc[nj][0] = -1e30f;
                if (col + 1 > qlocal)     sacc[nj][1] = -1e30f;
                if (col > qlocal + 8)     sacc[nj][2] = -1e30f;
                if (col + 1 > qlocal + 8) sacc[nj][3] = -1e30f;
            }
        }

        // ---- online softmax ----
        #pragma unroll
        for (int r = 0; r < 2; r++) {
            float mt = -1e30f;
            #pragma unroll
            for (int nj = 0; nj < 8; nj++)
                mt = fmaxf(mt, fmaxf(sacc[nj][2 * r], sacc[nj][2 * r + 1]));
            mt = fmaxf(mt, __shfl_xor_sync(0xFFFFFFFFu, mt, 1));
            mt = fmaxf(mt, __shfl_xor_sync(0xFFFFFFFFu, mt, 2));
            const float mnew = fmaxf(mr[r], mt);
            const float alpha = __expf(mr[r] - mnew);
            mr[r] = mnew;
            lr[r] *= alpha;
            #pragma unroll
            for (int nj = 0; nj < 8; nj++) {
                o[nj][2 * r] *= alpha;
                o[nj][2 * r + 1] *= alpha;
            }
            float psum = 0.f;
            #pragma unroll
            for (int nj = 0; nj < 8; nj++) {
                const float p0 = __expf(sacc[nj][2 * r] - mnew);
                const float p1 = __expf(sacc[nj][2 * r + 1] - mnew);
                sacc[nj][2 * r] = p0;
                sacc[nj][2 * r + 1] = p1;
                psum += p0 + p1;
            }
            lr[r] += psum;
        }

        // ---- P fragments ----
        uint32_t ap[4][4];
        #pragma unroll
        for (int kp = 0; kp < 4; kp++) {
            const int nj = 2 * kp;
            __half2 t0 = __float22half2_rn(make_float2(sacc[nj][0], sacc[nj][1]));
            __half2 t1 = __float22half2_rn(make_float2(sacc[nj][2], sacc[nj][3]));
            __half2 t2 = __float22half2_rn(make_float2(sacc[nj + 1][0], sacc[nj + 1][1]));
            __half2 t3 = __float22half2_rn(make_float2(sacc[nj + 1][2], sacc[nj + 1][3]));
            ap[kp][0] = *(uint32_t*)&t0;
            ap[kp][1] = *(uint32_t*)&t1;
            ap[kp][2] = *(uint32_t*)&t2;
            ap[kp][3] = *(uint32_t*)&t3;
        }

        // ---- O += P V  (trans-ldmatrix: n-tile0=(r0,r2), n-tile1=(r1,r3)) ----
        #pragma unroll
        for (int kp = 0; kp < 4; kp++) {
            uint32_t bv[4][4];
            #pragma unroll
            for (int pd = 0; pd < 4; pd++) {
                const int row = kp * 16 + (lane & 7) + ((lane >> 4) << 3);
                const int col = pd * 16 + (((lane >> 3) & 1) << 3);
                ldsm4t(bv[pd], sV + (uint32_t)(row * SV + col) * 2);
            }
            #pragma unroll
            for (int pd = 0; pd < 4; pd++) {
                mma_f16(o[2 * pd],     ap[kp], bv[pd][0], bv[pd][2]);
                mma_f16(o[2 * pd + 1], ap[kp], bv[pd][1], bv[pd][3]);
            }
        }
        __syncthreads();
    }

    // ---- epilogue: normalize + fp16 hi/lo ----
    float inv[2];
    #pragma unroll
    for (int r = 0; r < 2; r++) {
        float ls = lr[r];
        ls += __shfl_xor_sync(0xFFFFFFFFu, ls, 1);
        ls += __shfl_xor_sync(0xFFFFFFFFu, ls, 2);
        inv[r] = 1.0f / ls;
    }
    #pragma unroll
    for (int r = 0; r < 2; r++) {
        const int trow = qt * 64 + wid * 16 + (lane >> 2) + 8 * r;
        const size_t rowoff = (size_t)(b * SEQT + trow) * EMB + h * HDIM;
        #pragma unroll
        for (int nj = 0; nj < 8; nj++) {
            const int col = nj * 8 + 2 * (lane & 3);
            const float v0 = o[nj][2 * r] * inv[r];
            const float v1 = o[nj][2 * r + 1] * inv[r];
            const __half h0 = __float2half_rn(v0);
            const __half h1 = __float2half_rn(v1);
            const __half l0 = __float2half_rn(v0 - __half2float(h0));
            const __half l1 = __float2half_rn(v1 - __half2float(h1));
            __half2 ph; ph.x = h0; ph.y = h1;
            __half2 pl; pl.x = l0; pl.y = l1;
            *(__half2*)&outh[rowoff + col] = ph;
            *(__half2*)&outl[rowoff + col] = pl;
        }
    }
}

// ---------------------------------------------------------------------------
// Launch sequence
// ---------------------------------------------------------------------------
extern "C" void kernel_launch(void* const* d_in, const int* in_sizes, int n_in,
                              void* d_out, int out_size)
{
    const float* x  = (const float*)d_in[0];
    const float* W1 = (const float*)d_in[1];
    const float* W2 = (const float*)d_in[2];
    float* out = (float*)d_out;

    void *p_qkv, *p_xh, *p_xl, *p_w1, *p_w2, *p_ah, *p_al, *p_qh, *p_kh, *p_vh;
    cudaGetSymbolAddress(&p_qkv, g_qkv);
    cudaGetSymbolAddress(&p_xh, g_xh); cudaGetSymbolAddress(&p_xl, g_xl);
    cudaGetSymbolAddress(&p_w1, g_w1); cudaGetSymbolAddress(&p_w2, g_w2);
    cudaGetSymbolAddress(&p_ah, g_ah); cudaGetSymbolAddress(&p_al, g_al);
    cudaGetSymbolAddress(&p_qh, g_qh); cudaGetSymbolAddress(&p_kh, g_kh);
    cudaGetSymbolAddress(&p_vh, g_vh);

    cudaFuncSetAttribute(gemm_f16x2<true>,  cudaFuncAttributeMaxDynamicSharedMemorySize, GEMM_SMEM);
    cudaFuncSetAttribute(gemm_f16x2<false>, cudaFuncAttributeMaxDynamicSharedMemorySize, GEMM_SMEM);

    // conversions
    convert_hilo_f16<<<(MROWS * KDIM / 4 + 255) / 256, 256>>>(
        x, (__half*)p_xh, (__half*)p_xl, MROWS * KDIM / 4);
    convert_f16<<<(E3 * KDIM / 4 + 255) / 256, 256>>>(W1, (__half*)p_w1, E3 * KDIM / 4);
    convert_f16<<<(EMB * KDIM / 4 + 255) / 256, 256>>>(W2, (__half*)p_w2, EMB * KDIM / 4);

    // qkv = x @ W1^T  (fp16 out)
    {
        dim3 g(E3 / GBN, MROWS / GBM);
        gemm_f16x2<true><<<g, 256, GEMM_SMEM>>>(
            (const __half*)p_xh, (const __half*)p_xl, (const __half*)p_w1, p_qkv, E3);
    }

    // RoPE + repack
    rope_repack<<<(BATCH * SEQT * NHEAD * 32) / 256, 256>>>(
        (const __half*)p_qkv, (__half*)p_qh, (__half*)p_kh, (__half*)p_vh);

    // attention -> fp16 hi/lo
    {
        dim3 ga(SEQT / 64, BATCH * NHEAD);
        attn_mma<<<ga, 128>>>((const __half*)p_qh, (const __half*)p_kh,
                              (const __half*)p_vh, (__half*)p_ah, (__half*)p_al);
    }

    // out = att @ W2^T  (fp32 out)
    {
        dim3 g(EMB / GBN, MROWS / GBM);
        gemm_f16x2<false><<<g, 256, GEMM_SMEM>>>(
            (const __half*)p_ah, (const __half*)p_al, (const __half*)p_w2, out, EMB);
    }
}

// round 8
// speedup vs baseline: 6.7488x; 1.1644x over previous
#include <cuda_runtime.h>
#include <cuda_fp16.h>
#include <math.h>
#include <stdint.h>

// ---------------------------------------------------------------------------
// Problem constants
// ---------------------------------------------------------------------------
#define BATCH 2
#define SEQT  2048
#define EMB   1024
#define NHEAD 16
#define HDIM  64
#define E3    3072
#define MROWS (BATCH*SEQT)   // 4096
#define KDIM  1024

// ---------------------------------------------------------------------------
// Scratch (__device__ globals; no runtime allocation)
// ---------------------------------------------------------------------------
__device__ __half g_qkv[(size_t)MROWS * E3];                 // fp16 qkv
__device__ __half g_x16[(size_t)MROWS * KDIM];               // x fp16
__device__ __half g_w1[(size_t)E3 * KDIM];                   // W1 fp16
__device__ __half g_w2[(size_t)EMB * KDIM];                  // W2 fp16
__device__ __half g_ah[(size_t)MROWS * KDIM];                // attn out hi
__device__ __half g_al[(size_t)MROWS * KDIM];                // attn out lo
__device__ __half g_qh[(size_t)BATCH * NHEAD * SEQT * HDIM]; // q (scaled, rope)
__device__ __half g_kh[(size_t)BATCH * NHEAD * SEQT * HDIM]; // k (rope)
__device__ __half g_vh[(size_t)BATCH * NHEAD * SEQT * HDIM]; // v

// ---------------------------------------------------------------------------
// Helpers
// ---------------------------------------------------------------------------
__device__ __forceinline__ uint32_t smem_u32(const void* p) {
    uint32_t a;
    asm("{ .reg .u64 t; cvta.to.shared.u64 t, %1; cvt.u32.u64 %0, t; }" : "=r"(a) : "l"(p));
    return a;
}
__device__ __forceinline__ void cp_async16(uint32_t dst, const void* src) {
    asm volatile("cp.async.cg.shared.global [%0], [%1], 16;" :: "r"(dst), "l"(src));
}
__device__ __forceinline__ void cp_commit() {
    asm volatile("cp.async.commit_group;" ::: "memory");
}
template <int N> __device__ __forceinline__ void cp_wait() {
    asm volatile("cp.async.wait_group %0;" :: "n"(N) : "memory");
}
__device__ __forceinline__ void ldsm4(uint32_t* r, uint32_t addr) {
    asm volatile("ldmatrix.sync.aligned.m8n8.x4.shared.b16 {%0,%1,%2,%3}, [%4];"
        : "=r"(r[0]), "=r"(r[1]), "=r"(r[2]), "=r"(r[3]) : "r"(addr));
}
__device__ __forceinline__ void ldsm4t(uint32_t* r, uint32_t addr) {
    asm volatile("ldmatrix.sync.aligned.m8n8.x4.trans.shared.b16 {%0,%1,%2,%3}, [%4];"
        : "=r"(r[0]), "=r"(r[1]), "=r"(r[2]), "=r"(r[3]) : "r"(addr));
}
__device__ __forceinline__ void mma_f16(float* c, const uint32_t* a, uint32_t b0, uint32_t b1) {
    asm volatile(
        "mma.sync.aligned.m16n8k16.row.col.f32.f16.f16.f32 "
        "{%0,%1,%2,%3}, {%4,%5,%6,%7}, {%8,%9}, {%0,%1,%2,%3};"
        : "+f"(c[0]), "+f"(c[1]), "+f"(c[2]), "+f"(c[3])
        : "r"(a[0]), "r"(a[1]), "r"(a[2]), "r"(a[3]), "r"(b0), "r"(b1));
}

// ---------------------------------------------------------------------------
// Conversions
// ---------------------------------------------------------------------------
__global__ void convert_f16(const float* __restrict__ src,
                            __half* __restrict__ dst, int n4)
{
    int i = blockIdx.x * blockDim.x + threadIdx.x;
    if (i >= n4) return;
    float4 v = ((const float4*)src)[i];
    __half2* dp = (__half2*)dst;
    dp[2 * i]     = __floats2half2_rn(v.x, v.y);
    dp[2 * i + 1] = __floats2half2_rn(v.z, v.w);
}

// ---------------------------------------------------------------------------
// fp16 mma GEMM. C[M,N] = A[M,K] @ B[N,K]^T.
// COMP: A is (Ah + Al) hi/lo pair -> 2 MMA passes (used for output proj).
// 128x128x32 tiles, 256 threads (8 warps 4m x 2n), 3-stage cp.async ring.
// ---------------------------------------------------------------------------
#define GBM 128
#define GBN 128
#define GBK 32
#define GSK 40                        // padded smem stride (halves)
#define GMAT (GBM * GSK)              // 5120 halves per matrix tile

template <bool COMP>
__device__ __forceinline__ void g2_load(
    uint32_t s0, int tid, int kc, int m0, int n0,
    const __half* __restrict__ Ah, const __half* __restrict__ Al,
    const __half* __restrict__ B)
{
    const __half* a0 = Ah + (size_t)m0 * KDIM + kc * GBK;
    const __half* b0 = B  + (size_t)n0 * KDIM + kc * GBK;
    const __half* a1 = COMP ? (Al + (size_t)m0 * KDIM + kc * GBK) : nullptr;
    #pragma unroll
    for (int it = 0; it < 2; it++) {
        const int jj = tid + it * 256;      // 0..511
        const int row = jj >> 2;
        const int c = jj & 3;
        const uint32_t d = s0 + (uint32_t)(row * GSK + c * 8) * 2;
        const size_t goff = (size_t)row * KDIM + c * 8;
        cp_async16(d, a0 + goff);
        if (COMP) cp_async16(d + GMAT * 2, a1 + goff);
        cp_async16(d + (COMP ? 2 : 1) * GMAT * 2, b0 + goff);
    }
    cp_commit();
}

template <bool HALF_OUT, bool COMP>
__global__ void __launch_bounds__(256, 2)
gemm_f16(const __half* __restrict__ Ah, const __half* __restrict__ Al,
         const __half* __restrict__ B, void* __restrict__ Cv, int N)
{
    constexpr uint32_t STAGE_B = (COMP ? 3 : 2) * GMAT * 2;
    extern __shared__ char smem[];
    const uint32_t sb = smem_u32(smem);
    const int tid = threadIdx.x;
    const int wid = tid >> 5;
    const int lane = tid & 31;
    const int wm = wid >> 1;    // 0..3
    const int wn = wid & 1;     // 0..1
    const int m0 = blockIdx.y * GBM;
    const int n0 = blockIdx.x * GBN;

    float acc[2][8][4];
    #pragma unroll
    for (int i = 0; i < 2; i++)
        #pragma unroll
        for (int j = 0; j < 8; j++)
            #pragma unroll
            for (int k = 0; k < 4; k++) acc[i][j][k] = 0.f;

    g2_load<COMP>(sb,           tid, 0, m0, n0, Ah, Al, B);
    g2_load<COMP>(sb + STAGE_B, tid, 1, m0, n0, Ah, Al, B);

    const int NCH = KDIM / GBK;   // 32
    for (int c = 0; c < NCH; c++) {
        if (c + 1 < NCH) cp_wait<1>(); else cp_wait<0>();
        __syncthreads();

        const uint32_t scur = sb + (uint32_t)(c % 3) * STAGE_B;
        const uint32_t sAh = scur;
        const uint32_t sAl = scur + GMAT * 2;                  // valid iff COMP
        const uint32_t sB  = scur + (COMP ? 2 : 1) * GMAT * 2;

        #pragma unroll
        for (int ks = 0; ks < 2; ks++) {
            const int k0 = ks * 16;
            uint32_t aH[2][4], aL[2][4];
            #pragma unroll
            for (int mi = 0; mi < 2; mi++) {
                const int row = wm * 32 + mi * 16 + (lane & 15);
                const int col = k0 + ((lane >> 4) << 3);
                const uint32_t off = (uint32_t)(row * GSK + col) * 2;
                ldsm4(aH[mi], sAh + off);
                if (COMP) ldsm4(aL[mi], sAl + off);
            }
            #pragma unroll
            for (int p = 0; p < 4; p++) {
                uint32_t bb[4];
                const int row = wn * 64 + p * 16 + (lane & 7) + ((lane >> 4) << 3);
                const int col = k0 + (((lane >> 3) & 1) << 3);
                ldsm4(bb, sB + (uint32_t)(row * GSK + col) * 2);
                #pragma unroll
                for (int mi = 0; mi < 2; mi++) {
                    mma_f16(acc[mi][2 * p],     aH[mi], bb[0], bb[1]);
                    mma_f16(acc[mi][2 * p + 1], aH[mi], bb[2], bb[3]);
                    if (COMP) {
                        mma_f16(acc[mi][2 * p],     aL[mi], bb[0], bb[1]);
                        mma_f16(acc[mi][2 * p + 1], aL[mi], bb[2], bb[3]);
                    }
                }
            }
        }
        if (c + 2 < NCH)
            g2_load<COMP>(sb + (uint32_t)((c + 2) % 3) * STAGE_B, tid, c + 2, m0, n0, Ah, Al, B);
    }

    // Epilogue
    #pragma unroll
    for (int mi = 0; mi < 2; mi++) {
        const int r0 = m0 + wm * 32 + mi * 16 + (lane >> 2);
        #pragma unroll
        for (int nj = 0; nj < 8; nj++) {
            const int col = n0 + wn * 64 + nj * 8 + 2 * (lane & 3);
            if (HALF_OUT) {
                __half* C = (__half*)Cv;
                *(__half2*)&C[(size_t)r0 * N + col] =
                    __floats2half2_rn(acc[mi][nj][0], acc[mi][nj][1]);
                *(__half2*)&C[(size_t)(r0 + 8) * N + col] =
                    __floats2half2_rn(acc[mi][nj][2], acc[mi][nj][3]);
            } else {
                float* C = (float*)Cv;
                *(float2*)&C[(size_t)r0 * N + col] = make_float2(acc[mi][nj][0], acc[mi][nj][1]);
                *(float2*)&C[(size_t)(r0 + 8) * N + col] = make_float2(acc[mi][nj][2], acc[mi][nj][3]);
            }
        }
    }
}

#define GEMM1_SMEM (3 * 2 * GMAT * 2)   // 61440
#define GEMM2_SMEM (3 * 3 * GMAT * 2)   // 92160

// ---------------------------------------------------------------------------
// RoPE + repack fp16 qkv -> fp16 [b][h][t][d].
// q gets 0.125 * log2(e) folded in (softmax runs in exp2 domain).
// ---------------------------------------------------------------------------
#define QSCALE 0.18033688011112042f   // 0.125 * log2(e)

__global__ void rope_repack(const __half* __restrict__ qkv,
                            __half* __restrict__ qh, __half* __restrict__ kh,
                            __half* __restrict__ vh)
{
    const int idx = blockIdx.x * blockDim.x + threadIdx.x;
    const int j = idx & 31;
    const int h = (idx >> 5) & 15;
    const int t = (idx >> 9) & 2047;
    const int b = idx >> 20;

    const float inv_freq = exp2f(-(float)j * (13.287712379549449f / 32.0f));
    float s, c;
    sincosf((float)t * inv_freq, &s, &c);

    const __half* p = qkv + ((size_t)(b * SEQT + t)) * E3 + h * HDIM + j;
    const float q0 = __half2float(p[0]),       q1 = __half2float(p[32]);
    const float k0 = __half2float(p[EMB]),     k1 = __half2float(p[EMB + 32]);
    const float v0 = __half2float(p[2 * EMB]), v1 = __half2float(p[2 * EMB + 32]);

    const size_t o = ((size_t)((b * NHEAD + h) * SEQT + t)) * HDIM + j;
    qh[o]      = __float2half(QSCALE * (q0 * c - q1 * s));
    qh[o + 32] = __float2half(QSCALE * (q1 * c + q0 * s));
    kh[o]      = __float2half(k0 * c - k1 * s);
    kh[o + 32] = __float2half(k1 * c + k0 * s);
    vh[o]      = __float2half(v0);
    vh[o + 32] = __float2half(v1);
}

// ---------------------------------------------------------------------------
// fp16 mma causal flash attention. 256 threads (8 warps), 128 queries per
// block (warp = m16). K-tile = 64, double-buffered cp.async.
// Softmax in exp2 domain. Fully-masked warp tiles skip compute.
// Dynamic smem: Q[128*SV] | K[2][64*SV] | V[2][64*SV]  (55296 bytes).
// Output fp16 hi/lo into [b][t][h*64+d].
// ---------------------------------------------------------------------------
#define SV 72   // smem row stride (halves)
#define AQT 128
#define ATTN_SQ_OFF 0
#define ATTN_SK_OFF (AQT * SV * 2)                    // 18432
#define ATTN_SV_OFF (ATTN_SK_OFF + 2 * 64 * SV * 2)   // 36864
#define ATTN_SMEM   (ATTN_SV_OFF + 2 * 64 * SV * 2)   // 55296

__global__ void __launch_bounds__(256, 2) attn_mma(
    const __half* __restrict__ qh, const __half* __restrict__ kh,
    const __half* __restrict__ vh,
    __half* __restrict__ outh, __half* __restrict__ outl)
{
    extern __shared__ char asmem[];
    const uint32_t sbase = smem_u32(asmem);
    const uint32_t sQ = sbase + ATTN_SQ_OFF;
    const uint32_t sKb[2] = { sbase + ATTN_SK_OFF, sbase + ATTN_SK_OFF + 64 * SV * 2 };
    const uint32_t sVb[2] = { sbase + ATTN_SV_OFF, sbase + ATTN_SV_OFF + 64 * SV * 2 };

    const int bh = blockIdx.y;
    const int b = bh >> 4;
    const int h = bh & 15;
    const int qt = (gridDim.x - 1) - blockIdx.x;   // heavy tiles first
    const int tid = threadIdx.x;
    const int wid = tid >> 5;
    const int lane = tid & 31;

    const __half* qg = qh + (size_t)bh * SEQT * HDIM;
    const __half* kg = kh + (size_t)bh * SEQT * HDIM;
    const __half* vg = vh + (size_t)bh * SEQT * HDIM;

    // Load Q tile: 128 rows x 8 chunks = 1024 chunks, 4/thread
    #pragma unroll
    for (int i = 0; i < 4; i++) {
        const int ch = tid + i * 256;
        const int row = ch >> 3;
        const int c = ch & 7;
        cp_async16(sQ + (uint32_t)(row * SV + c * 8) * 2,
                   qg + (size_t)(qt * AQT + row) * HDIM + c * 8);
    }
    cp_commit();

    // Prefetch K/V tile 0 (512 chunks each, 2/thread)
    {
        #pragma unroll
        for (int i = 0; i < 2; i++) {
            const int ch = tid + i * 256;
            const int row = ch >> 3;
            const int c = ch & 7;
            const uint32_t d = (uint32_t)(row * SV + c * 8) * 2;
            const size_t goff = (size_t)row * HDIM + c * 8;
            cp_async16(sKb[0] + d, kg + goff);
            cp_async16(sVb[0] + d, vg + goff);
        }
        cp_commit();
    }

    cp_wait<1>();   // Q ready
    __syncthreads();

    uint32_t aq[4][4];
    #pragma unroll
    for (int ks = 0; ks < 4; ks++) {
        const int row = wid * 16 + (lane & 15);
        const int col = ks * 16 + ((lane >> 4) << 3);
        ldsm4(aq[ks], sQ + (uint32_t)(row * SV + col) * 2);
    }

    float o[8][4];
    #pragma unroll
    for (int j = 0; j < 8; j++)
        #pragma unroll
        for (int k = 0; k < 4; k++) o[j][k] = 0.f;
    float mr[2] = {-1e30f, -1e30f};
    float lr[2] = {0.f, 0.f};

    const int q0g = qt * AQT + wid * 16;       // first query row of this warp
    const int NKT = 2 * qt + 2;                // k-tiles to visit

    for (int kt = 0; kt < NKT; kt++) {
        const int cb = kt & 1;
        if (kt + 1 < NKT) {
            const uint32_t sKn = sKb[1 - cb];
            const uint32_t sVn = sVb[1 - cb];
            #pragma unroll
            for (int i = 0; i < 2; i++) {
                const int ch = tid + i * 256;
                const int row = ch >> 3;
                const int c = ch & 7;
                const uint32_t d = (uint32_t)(row * SV + c * 8) * 2;
                const size_t goff = (size_t)((kt + 1) * 64 + row) * HDIM + c * 8;
                cp_async16(sKn + d, kg + goff);
                cp_async16(sVn + d, vg + goff);
            }
            cp_commit();
            cp_wait<1>();
        } else {
            cp_wait<0>();
        }
        __syncthreads();

        const int kbase = kt * 64;
        const bool active = (kbase <= q0g + 15);   // any unmasked key for warp?
        if (active) {
            const uint32_t sK = sKb[cb];
            const uint32_t sV = sVb[cb];

            // ---- S = Q K^T ----
            float sacc[8][4];
            #pragma unroll
            for (int j = 0; j < 8; j++)
                #pragma unroll
                for (int k = 0; k < 4; k++) sacc[j][k] = 0.f;

            #pragma unroll
            for (int ks = 0; ks < 4; ks++) {
                uint32_t bk[4][4];
                #pragma unroll
                for (int p = 0; p < 4; p++) {
                    const int row = p * 16 + (lane & 7) + ((lane >> 4) << 3);
                    const int col = ks * 16 + (((lane >> 3) & 1) << 3);
                    ldsm4(bk[p], sK + (uint32_t)(row * SV + col) * 2);
                }
                #pragma unroll
                for (int p = 0; p < 4; p++) {
                    mma_f16(sacc[2 * p],     aq[ks], bk[p][0], bk[p][1]);
                    mma_f16(sacc[2 * p + 1], aq[ks], bk[p][2], bk[p][3]);
                }
            }

            // ---- causal mask (possibly-diagonal tiles) ----
            if (kbase + 63 > q0g) {
                const int qg0 = q0g + (lane >> 2);   // r=0 global query row
                #pragma unroll
                for (int nj = 0; nj < 8; nj++) {
                    const int col = kbase + nj * 8 + 2 * (lane & 3);
                    if (col > qg0)         sacc[nj][0] = -1e30f;
                    if (col + 1 > qg0)     sacc[nj][1] = -1e30f;
                    if (col > qg0 + 8)     sacc[nj][2] = -1e30f;
                    if (col + 1 > qg0 + 8) sacc[nj][3] = -1e30f;
                }
            }

            // ---- online softmax (exp2 domain) ----
            #pragma unroll
            for (int r = 0; r < 2; r++) {
                float mt = -1e30f;
                #pragma unroll
                for (int nj = 0; nj < 8; nj++)
                    mt = fmaxf(mt, fmaxf(sacc[nj][2 * r], sacc[nj][2 * r + 1]));
                mt = fmaxf(mt, __shfl_xor_sync(0xFFFFFFFFu, mt, 1));
                mt = fmaxf(mt, __shfl_xor_sync(0xFFFFFFFFu, mt, 2));
                const float mnew = fmaxf(mr[r], mt);
                const float alpha = exp2f(mr[r] - mnew);
                mr[r] = mnew;
                lr[r] *= alpha;
                #pragma unroll
                for (int nj = 0; nj < 8; nj++) {
                    o[nj][2 * r] *= alpha;
                    o[nj][2 * r + 1] *= alpha;
                }
                float psum = 0.f;
                #pragma unroll
                for (int nj = 0; nj < 8; nj++) {
                    const float p0 = exp2f(sacc[nj][2 * r] - mnew);
                    const float p1 = exp2f(sacc[nj][2 * r + 1] - mnew);
                    sacc[nj][2 * r] = p0;
                    sacc[nj][2 * r + 1] = p1;
                    psum += p0 + p1;
                }
                lr[r] += psum;
            }

            // ---- P fragments ----
            uint32_t ap[4][4];
            #pragma unroll
            for (int kp = 0; kp < 4; kp++) {
                const int nj = 2 * kp;
                __half2 t0 = __float22half2_rn(make_float2(sacc[nj][0], sacc[nj][1]));
                __half2 t1 = __float22half2_rn(make_float2(sacc[nj][2], sacc[nj][3]));
                __half2 t2 = __float22half2_rn(make_float2(sacc[nj + 1][0], sacc[nj + 1][1]));
                __half2 t3 = __float22half2_rn(make_float2(sacc[nj + 1][2], sacc[nj + 1][3]));
                ap[kp][0] = *(uint32_t*)&t0;
                ap[kp][1] = *(uint32_t*)&t1;
                ap[kp][2] = *(uint32_t*)&t2;
                ap[kp][3] = *(uint32_t*)&t3;
            }

            // ---- O += P V  (trans-ldmatrix: n-tile0=(r0,r2), n-tile1=(r1,r3)) ----
            #pragma unroll
            for (int kp = 0; kp < 4; kp++) {
                uint32_t bv[4][4];
                #pragma unroll
                for (int pd = 0; pd < 4; pd++) {
                    const int row = kp * 16 + (lane & 7) + ((lane >> 4) << 3);
                    const int col = pd * 16 + (((lane >> 3) & 1) << 3);
                    ldsm4t(bv[pd], sV + (uint32_t)(row * SV + col) * 2);
                }
                #pragma unroll
                for (int pd = 0; pd < 4; pd++) {
                    mma_f16(o[2 * pd],     ap[kp], bv[pd][0], bv[pd][2]);
                    mma_f16(o[2 * pd + 1], ap[kp], bv[pd][1], bv[pd][3]);
                }
            }
        }
        __syncthreads();
    }

    // ---- epilogue: normalize + fp16 hi/lo ----
    float inv[2];
    #pragma unroll
    for (int r = 0; r < 2; r++) {
        float ls = lr[r];
        ls += __shfl_xor_sync(0xFFFFFFFFu, ls, 1);
        ls += __shfl_xor_sync(0xFFFFFFFFu, ls, 2);
        inv[r] = 1.0f / ls;
    }
    #pragma unroll
    for (int r = 0; r < 2; r++) {
        const int trow = qt * AQT + wid * 16 + (lane >> 2) + 8 * r;
        const size_t rowoff = (size_t)(b * SEQT + trow) * EMB + h * HDIM;
        #pragma unroll
        for (int nj = 0; nj < 8; nj++) {
            const int col = nj * 8 + 2 * (lane & 3);
            const float v0 = o[nj][2 * r] * inv[r];
            const float v1 = o[nj][2 * r + 1] * inv[r];
            const __half h0 = __float2half_rn(v0);
            const __half h1 = __float2half_rn(v1);
            const __half l0 = __float2half_rn(v0 - __half2float(h0));
            const __half l1 = __float2half_rn(v1 - __half2float(h1));
            __half2 ph; ph.x = h0; ph.y = h1;
            __half2 pl; pl.x = l0; pl.y = l1;
            *(__half2*)&outh[rowoff + col] = ph;
            *(__half2*)&outl[rowoff + col] = pl;
        }
    }
}

// ---------------------------------------------------------------------------
// Launch sequence
// ---------------------------------------------------------------------------
extern "C" void kernel_launch(void* const* d_in, const int* in_sizes, int n_in,
                              void* d_out, int out_size)
{
    const float* x  = (const float*)d_in[0];
    const float* W1 = (const float*)d_in[1];
    const float* W2 = (const float*)d_in[2];
    float* out = (float*)d_out;

    void *p_qkv, *p_x16, *p_w1, *p_w2, *p_ah, *p_al, *p_qh, *p_kh, *p_vh;
    cudaGetSymbolAddress(&p_qkv, g_qkv);
    cudaGetSymbolAddress(&p_x16, g_x16);
    cudaGetSymbolAddress(&p_w1, g_w1); cudaGetSymbolAddress(&p_w2, g_w2);
    cudaGetSymbolAddress(&p_ah, g_ah); cudaGetSymbolAddress(&p_al, g_al);
    cudaGetSymbolAddress(&p_qh, g_qh); cudaGetSymbolAddress(&p_kh, g_kh);
    cudaGetSymbolAddress(&p_vh, g_vh);

    cudaFuncSetAttribute(gemm_f16<true, false>,
                         cudaFuncAttributeMaxDynamicSharedMemorySize, GEMM1_SMEM);
    cudaFuncSetAttribute(gemm_f16<false, true>,
                         cudaFuncAttributeMaxDynamicSharedMemorySize, GEMM2_SMEM);
    cudaFuncSetAttribute(attn_mma,
                         cudaFuncAttributeMaxDynamicSharedMemorySize, ATTN_SMEM);

    // conversions
    convert_f16<<<(MROWS * KDIM / 4 + 255) / 256, 256>>>(x,  (__half*)p_x16, MROWS * KDIM / 4);
    convert_f16<<<(E3 * KDIM / 4 + 255) / 256, 256>>>(W1, (__half*)p_w1, E3 * KDIM / 4);
    convert_f16<<<(EMB * KDIM / 4 + 255) / 256, 256>>>(W2, (__half*)p_w2, EMB * KDIM / 4);

    // qkv = x @ W1^T  (fp16 out, single MMA pass)
    {
        dim3 g(E3 / GBN, MROWS / GBM);
        gemm_f16<true, false><<<g, 256, GEMM1_SMEM>>>(
            (const __half*)p_x16, nullptr, (const __half*)p_w1, p_qkv, E3);
    }

    // RoPE + repack (exp2-domain scale folded into q)
    rope_repack<<<(BATCH * SEQT * NHEAD * 32) / 256, 256>>>(
        (const __half*)p_qkv, (__half*)p_qh, (__half*)p_kh, (__half*)p_vh);

    // attention -> fp16 hi/lo
    {
        dim3 ga(SEQT / AQT, BATCH * NHEAD);
        attn_mma<<<ga, 256, ATTN_SMEM>>>((const __half*)p_qh, (const __half*)p_kh,
                                         (const __half*)p_vh, (__half*)p_ah, (__half*)p_al);
    }

    // out = att @ W2^T  (fp32 out, compensated 2-MMA)
    {
        dim3 g(EMB / GBN, MROWS / GBM);
        gemm_f16<false, true><<<g, 256, GEMM2_SMEM>>>(
            (const __half*)p_ah, (const __half*)p_al, (const __half*)p_w2, out, EMB);
    }
}

// round 10
// speedup vs baseline: 7.6182x; 1.1288x over previous
#include <cuda_runtime.h>
#include <cuda_fp16.h>
#include <math.h>
#include <stdint.h>

// ---------------------------------------------------------------------------
// Problem constants
// ---------------------------------------------------------------------------
#define BATCH 2
#define SEQT  2048
#define EMB   1024
#define NHEAD 16
#define HDIM  64
#define E3    3072
#define MROWS (BATCH*SEQT)   // 4096
#define KDIM  1024

// ---------------------------------------------------------------------------
// Scratch (__device__ globals; no runtime allocation)
// ---------------------------------------------------------------------------
__device__ __half g_x16[(size_t)MROWS * KDIM];               // x fp16
__device__ __half g_w1[(size_t)E3 * KDIM];                   // W1 fp16
__device__ __half g_w2[(size_t)EMB * KDIM];                  // W2 fp16
__device__ __half g_ah[(size_t)MROWS * KDIM];                // attn out
__device__ __half g_qh[(size_t)BATCH * NHEAD * SEQT * HDIM]; // q (scaled, rope)
__device__ __half g_kh[(size_t)BATCH * NHEAD * SEQT * HDIM]; // k (rope)
__device__ __half g_vh[(size_t)BATCH * NHEAD * SEQT * HDIM]; // v

#define QSCALE 0.18033688011112042f   // 0.125 * log2(e)
#define LOG2_10000_OVER32 (13.287712379549449f / 32.0f)

// ---------------------------------------------------------------------------
// Helpers
// ---------------------------------------------------------------------------
__device__ __forceinline__ uint32_t smem_u32(const void* p) {
    uint32_t a;
    asm("{ .reg .u64 t; cvta.to.shared.u64 t, %1; cvt.u32.u64 %0, t; }" : "=r"(a) : "l"(p));
    return a;
}
__device__ __forceinline__ void cp_async16(uint32_t dst, const void* src) {
    asm volatile("cp.async.cg.shared.global [%0], [%1], 16;" :: "r"(dst), "l"(src));
}
__device__ __forceinline__ void cp_commit() {
    asm volatile("cp.async.commit_group;" ::: "memory");
}
template <int N> __device__ __forceinline__ void cp_wait() {
    asm volatile("cp.async.wait_group %0;" :: "n"(N) : "memory");
}
__device__ __forceinline__ void ldsm4(uint32_t* r, uint32_t addr) {
    asm volatile("ldmatrix.sync.aligned.m8n8.x4.shared.b16 {%0,%1,%2,%3}, [%4];"
        : "=r"(r[0]), "=r"(r[1]), "=r"(r[2]), "=r"(r[3]) : "r"(addr));
}
__device__ __forceinline__ void ldsm4t(uint32_t* r, uint32_t addr) {
    asm volatile("ldmatrix.sync.aligned.m8n8.x4.trans.shared.b16 {%0,%1,%2,%3}, [%4];"
        : "=r"(r[0]), "=r"(r[1]), "=r"(r[2]), "=r"(r[3]) : "r"(addr));
}
__device__ __forceinline__ void mma_f16(float* c, const uint32_t* a, uint32_t b0, uint32_t b1) {
    asm volatile(
        "mma.sync.aligned.m16n8k16.row.col.f32.f16.f16.f32 "
        "{%0,%1,%2,%3}, {%4,%5,%6,%7}, {%8,%9}, {%0,%1,%2,%3};"
        : "+f"(c[0]), "+f"(c[1]), "+f"(c[2]), "+f"(c[3])
        : "r"(a[0]), "r"(a[1]), "r"(a[2]), "r"(a[3]), "r"(b0), "r"(b1));
}

// ---------------------------------------------------------------------------
// Conversions
// ---------------------------------------------------------------------------
__global__ void convert_f16(const float* __restrict__ src,
                            __half* __restrict__ dst, int n4)
{
    int i = blockIdx.x * blockDim.x + threadIdx.x;
    if (i >= n4) return;
    float4 v = ((const float4*)src)[i];
    __half2* dp = (__half2*)dst;
    dp[2 * i]     = __floats2half2_rn(v.x, v.y);
    dp[2 * i + 1] = __floats2half2_rn(v.z, v.w);
}

// ---------------------------------------------------------------------------
// fp16 mma GEMM. C[M,N] = A[M,K] @ B[N,K]^T.
// MODE 0: fp32 C out.  MODE 2: fused RoPE+repack epilogue to qh/kh/vh.
// 128x128x32 tiles, 256 threads (8 warps 4m x 2n), 3-stage cp.async ring.
// ---------------------------------------------------------------------------
#define GBM 128
#define GBN 128
#define GBK 32
#define GSK 40                        // padded smem stride (halves)
#define GMAT (GBM * GSK)              // 5120 halves per matrix tile
#define GSTAGE (2 * GMAT * 2)         // A,B per stage = 20480 bytes
#define GEMM_SMEM (3 * GSTAGE)        // 61440 bytes

__device__ __forceinline__ void g2_load(
    uint32_t s0, int tid, int kc, int m0, int n0,
    const __half* __restrict__ A, const __half* __restrict__ B)
{
    const __half* a0 = A + (size_t)m0 * KDIM + kc * GBK;
    const __half* b0 = B + (size_t)n0 * KDIM + kc * GBK;
    #pragma unroll
    for (int it = 0; it < 2; it++) {
        const int jj = tid + it * 256;      // 0..511
        const int row = jj >> 2;
        const int c = jj & 3;
        const uint32_t d = s0 + (uint32_t)(row * GSK + c * 8) * 2;
        const size_t goff = (size_t)row * KDIM + c * 8;
        cp_async16(d, a0 + goff);
        cp_async16(d + GMAT * 2, b0 + goff);
    }
    cp_commit();
}

template <int MODE>
__global__ void __launch_bounds__(256, 2)
gemm_f16(const __half* __restrict__ A, const __half* __restrict__ B,
         float* __restrict__ C, int N,
         __half* __restrict__ qh, __half* __restrict__ kh, __half* __restrict__ vh)
{
    extern __shared__ char smem[];
    const uint32_t sb = smem_u32(smem);
    const int tid = threadIdx.x;
    const int wid = tid >> 5;
    const int lane = tid & 31;
    const int wm = wid >> 1;    // 0..3
    const int wn = wid & 1;     // 0..1
    const int m0 = blockIdx.y * GBM;
    const int n0 = blockIdx.x * GBN;

    float acc[2][8][4];
    #pragma unroll
    for (int i = 0; i < 2; i++)
        #pragma unroll
        for (int j = 0; j < 8; j++)
            #pragma unroll
            for (int k = 0; k < 4; k++) acc[i][j][k] = 0.f;

    g2_load(sb,          tid, 0, m0, n0, A, B);
    g2_load(sb + GSTAGE, tid, 1, m0, n0, A, B);

    const int NCH = KDIM / GBK;   // 32
    for (int c = 0; c < NCH; c++) {
        if (c + 1 < NCH) cp_wait<1>(); else cp_wait<0>();
        __syncthreads();

        const uint32_t scur = sb + (uint32_t)(c % 3) * GSTAGE;
        const uint32_t sA = scur;
        const uint32_t sB = scur + GMAT * 2;

        #pragma unroll
        for (int ks = 0; ks < 2; ks++) {
            const int k0 = ks * 16;
            uint32_t aF[2][4];
            #pragma unroll
            for (int mi = 0; mi < 2; mi++) {
                const int row = wm * 32 + mi * 16 + (lane & 15);
                const int col = k0 + ((lane >> 4) << 3);
                ldsm4(aF[mi], sA + (uint32_t)(row * GSK + col) * 2);
            }
            #pragma unroll
            for (int p = 0; p < 4; p++) {
                uint32_t bb[4];
                const int row = wn * 64 + p * 16 + (lane & 7) + ((lane >> 4) << 3);
                const int col = k0 + (((lane >> 3) & 1) << 3);
                ldsm4(bb, sB + (uint32_t)(row * GSK + col) * 2);
                #pragma unroll
                for (int mi = 0; mi < 2; mi++) {
                    mma_f16(acc[mi][2 * p],     aF[mi], bb[0], bb[1]);
                    mma_f16(acc[mi][2 * p + 1], aF[mi], bb[2], bb[3]);
                }
            }
        }
        if (c + 2 < NCH)
            g2_load(sb + (uint32_t)((c + 2) % 3) * GSTAGE, tid, c + 2, m0, n0, A, B);
    }

    if (MODE == 0) {
        // fp32 epilogue
        #pragma unroll
        for (int mi = 0; mi < 2; mi++) {
            const int r0 = m0 + wm * 32 + mi * 16 + (lane >> 2);
            #pragma unroll
            for (int nj = 0; nj < 8; nj++) {
                const int col = n0 + wn * 64 + nj * 8 + 2 * (lane & 3);
                *(float2*)&C[(size_t)r0 * N + col] = make_float2(acc[mi][nj][0], acc[mi][nj][1]);
                *(float2*)&C[(size_t)(r0 + 8) * N + col] = make_float2(acc[mi][nj][2], acc[mi][nj][3]);
            }
        }
    } else {
        // fused RoPE + repack epilogue.
        // This warp owns cols [cbase, cbase+64) = exactly one head of q, k, or v.
        const int cbase = n0 + wn * 64;
        const int sec = cbase >> 10;            // 0=q 1=k 2=v
        const int hd  = (cbase & 1023) >> 6;
        __half* dst = (sec == 0) ? qh : (sec == 1) ? kh : vh;

        // 8 distinct local cols j (pairs p: j0=p*8+2*(lane&3), j0+1), invfreq per j
        float invf[8];
        #pragma unroll
        for (int p = 0; p < 4; p++) {
            const int j0 = p * 8 + 2 * (lane & 3);
            invf[2 * p]     = exp2f(-(float)j0 * LOG2_10000_OVER32);
            invf[2 * p + 1] = exp2f(-(float)(j0 + 1) * LOG2_10000_OVER32);
        }

        #pragma unroll
        for (int mi = 0; mi < 2; mi++) {
            #pragma unroll
            for (int rr = 0; rr < 2; rr++) {
                const int r = m0 + wm * 32 + mi * 16 + (lane >> 2) + rr * 8;
                const int bb = r >> 11;
                const int t = r & 2047;
                __half* drow = dst + ((size_t)((bb * NHEAD + hd) * SEQT + t)) * HDIM;
                if (sec == 2) {
                    #pragma unroll
                    for (int nj = 0; nj < 8; nj++) {
                        const int j0 = nj * 8 + 2 * (lane & 3);
                        *(__half2*)&drow[j0] =
                            __floats2half2_rn(acc[mi][nj][2 * rr], acc[mi][nj][2 * rr + 1]);
                    }
                } else {
                    const float qs = (sec == 0) ? QSCALE : 1.0f;
                    const float tf = (float)t;
                    #pragma unroll
                    for (int p = 0; p < 4; p++) {
                        const int j0 = p * 8 + 2 * (lane & 3);
                        const float a0 = acc[mi][p][2 * rr];
                        const float a1 = acc[mi][p][2 * rr + 1];
                        const float b0 = acc[mi][p + 4][2 * rr];
                        const float b1 = acc[mi][p + 4][2 * rr + 1];
                        float s0, c0, s1, c1;
                        sincosf(tf * invf[2 * p], &s0, &c0);
                        sincosf(tf * invf[2 * p + 1], &s1, &c1);
                        *(__half2*)&drow[j0] =
                            __floats2half2_rn(qs * (a0 * c0 - b0 * s0),
                                              qs * (a1 * c1 - b1 * s1));
                        *(__half2*)&drow[j0 + 32] =
                            __floats2half2_rn(qs * (b0 * c0 + a0 * s0),
                                              qs * (b1 * c1 + a1 * s1));
                    }
                }
            }
        }
    }
}

// ---------------------------------------------------------------------------
// fp16 mma causal flash attention. 256 threads (8 warps), 128 queries per
// block. K-tile = 64, double-buffered cp.async. exp2-domain softmax.
// Fully-masked warp tiles skip compute. Dynamic smem 55296 B.
// Output fp16 into [b][t][h*64+d].
// ---------------------------------------------------------------------------
#define SV 72   // smem row stride (halves)
#define AQT 128
#define ATTN_SQ_OFF 0
#define ATTN_SK_OFF (AQT * SV * 2)                    // 18432
#define ATTN_SV_OFF (ATTN_SK_OFF + 2 * 64 * SV * 2)   // 36864
#define ATTN_SMEM   (ATTN_SV_OFF + 2 * 64 * SV * 2)   // 55296

__global__ void __launch_bounds__(256, 2) attn_mma(
    const __half* __restrict__ qh, const __half* __restrict__ kh,
    const __half* __restrict__ vh, __half* __restrict__ outh)
{
    extern __shared__ char asmem[];
    const uint32_t sbase = smem_u32(asmem);
    const uint32_t sQ = sbase + ATTN_SQ_OFF;
    const uint32_t sKb[2] = { sbase + ATTN_SK_OFF, sbase + ATTN_SK_OFF + 64 * SV * 2 };
    const uint32_t sVb[2] = { sbase + ATTN_SV_OFF, sbase + ATTN_SV_OFF + 64 * SV * 2 };

    const int bh = blockIdx.y;
    const int b = bh >> 4;
    const int h = bh & 15;
    const int qt = (gridDim.x - 1) - blockIdx.x;   // heavy tiles first
    const int tid = threadIdx.x;
    const int wid = tid >> 5;
    const int lane = tid & 31;

    const __half* qg = qh + (size_t)bh * SEQT * HDIM;
    const __half* kg = kh + (size_t)bh * SEQT * HDIM;
    const __half* vg = vh + (size_t)bh * SEQT * HDIM;

    // Load Q tile: 128 rows x 8 chunks = 1024 chunks, 4/thread
    #pragma unroll
    for (int i = 0; i < 4; i++) {
        const int ch = tid + i * 256;
        const int row = ch >> 3;
        const int c = ch & 7;
        cp_async16(sQ + (uint32_t)(row * SV + c * 8) * 2,
                   qg + (size_t)(qt * AQT + row) * HDIM + c * 8);
    }
    cp_commit();

    // Prefetch K/V tile 0 (512 chunks each, 2/thread)
    {
        #pragma unroll
        for (int i = 0; i < 2; i++) {
            const int ch = tid + i * 256;
            const int row = ch >> 3;
            const int c = ch & 7;
            const uint32_t d = (uint32_t)(row * SV + c * 8) * 2;
            const size_t goff = (size_t)row * HDIM + c * 8;
            cp_async16(sKb[0] + d, kg + goff);
            cp_async16(sVb[0] + d, vg + goff);
        }
        cp_commit();
    }

    cp_wait<1>();   // Q ready
    __syncthreads();

    uint32_t aq[4][4];
    #pragma unroll
    for (int ks = 0; ks < 4; ks++) {
        const int row = wid * 16 + (lane & 15);
        const int col = ks * 16 + ((lane >> 4) << 3);
        ldsm4(aq[ks], sQ + (uint32_t)(row * SV + col) * 2);
    }

    float o[8][4];
    #pragma unroll
    for (int j = 0; j < 8; j++)
        #pragma unroll
        for (int k = 0; k < 4; k++) o[j][k] = 0.f;
    float mr[2] = {-1e30f, -1e30f};
    float lr[2] = {0.f, 0.f};

    const int q0g = qt * AQT + wid * 16;       // first query row of this warp
    const int NKT = 2 * qt + 2;                // k-tiles to visit

    for (int kt = 0; kt < NKT; kt++) {
        const int cb = kt & 1;
        if (kt + 1 < NKT) {
            const uint32_t sKn = sKb[1 - cb];
            const uint32_t sVn = sVb[1 - cb];
            #pragma unroll
            for (int i = 0; i < 2; i++) {
                const int ch = tid + i * 256;
                const int row = ch >> 3;
                const int c = ch & 7;
                const uint32_t d = (uint32_t)(row * SV + c * 8) * 2;
                const size_t goff = (size_t)((kt + 1) * 64 + row) * HDIM + c * 8;
                cp_async16(sKn + d, kg + goff);
                cp_async16(sVn + d, vg + goff);
            }
            cp_commit();
            cp_wait<1>();
        } else {
            cp_wait<0>();
        }
        __syncthreads();

        const int kbase = kt * 64;
        const bool active = (kbase <= q0g + 15);   // any unmasked key for warp?
        if (active) {
            const uint32_t sK = sKb[cb];
            const uint32_t sV = sVb[cb];

            // ---- S = Q K^T ----
            float sacc[8][4];
            #pragma unroll
            for (int j = 0; j < 8; j++)
                #pragma unroll
                for (int k = 0; k < 4; k++) sacc[j][k] = 0.f;

            #pragma unroll
            for (int ks = 0; ks < 4; ks++) {
                uint32_t bk[4][4];
                #pragma unroll
                for (int p = 0; p < 4; p++) {
                    const int row = p * 16 + (lane & 7) + ((lane >> 4) << 3);
                    const int col = ks * 16 + (((lane >> 3) & 1) << 3);
                    ldsm4(bk[p], sK + (uint32_t)(row * SV + col) * 2);
                }
                #pragma unroll
                for (int p = 0; p < 4; p++) {
                    mma_f16(sacc[2 * p],     aq[ks], bk[p][0], bk[p][1]);
                    mma_f16(sacc[2 * p + 1], aq[ks], bk[p][2], bk[p][3]);
                }
            }

            // ---- causal mask (possibly-diagonal tiles) ----
            if (kbase + 63 > q0g) {
                const int qg0 = q0g + (lane >> 2);   // r=0 global query row
                #pragma unroll
                for (int nj = 0; nj < 8; nj++) {
                    const int col = kbase + nj * 8 + 2 * (lane & 3);
                    if (col > qg0)         sacc[nj][0] = -1e30f;
                    if (col + 1 > qg0)     sacc[nj][1] = -1e30f;
                    if (col > qg0 + 8)     sacc[nj][2] = -1e30f;
                    if (col + 1 > qg0 + 8) sacc[nj][3] = -1e30f;
                }
            }

            // ---- online softmax (exp2 domain) ----
            #pragma unroll
            for (int r = 0; r < 2; r++) {
                float mt = -1e30f;
                #pragma unroll
                for (int nj = 0; nj < 8; nj++)
                    mt = fmaxf(mt, fmaxf(sacc[nj][2 * r], sacc[nj][2 * r + 1]));
                mt = fmaxf(mt, __shfl_xor_sync(0xFFFFFFFFu, mt, 1));
                mt = fmaxf(mt, __shfl_xor_sync(0xFFFFFFFFu, mt, 2));
                const float mnew = fmaxf(mr[r], mt);
                const float alpha = exp2f(mr[r] - mnew);
                mr[r] = mnew;
                lr[r] *= alpha;
                #pragma unroll
                for (int nj = 0; nj < 8; nj++) {
                    o[nj][2 * r] *= alpha;
                    o[nj][2 * r + 1] *= alpha;
                }
                float psum = 0.f;
                #pragma unroll
                for (int nj = 0; nj < 8; nj++) {
                    const float p0 = exp2f(sacc[nj][2 * r] - mnew);
                    const float p1 = exp2f(sacc[nj][2 * r + 1] - mnew);
                    sacc[nj][2 * r] = p0;
                    sacc[nj][2 * r + 1] = p1;
                    psum += p0 + p1;
                }
                lr[r] += psum;
            }

            // ---- P fragments ----
            uint32_t ap[4][4];
            #pragma unroll
            for (int kp = 0; kp < 4; kp++) {
                const int nj = 2 * kp;
                __half2 t0 = __float22half2_rn(make_float2(sacc[nj][0], sacc[nj][1]));
                __half2 t1 = __float22half2_rn(make_float2(sacc[nj][2], sacc[nj][3]));
                __half2 t2 = __float22half2_rn(make_float2(sacc[nj + 1][0], sacc[nj + 1][1]));
                __half2 t3 = __float22half2_rn(make_float2(sacc[nj + 1][2], sacc[nj + 1][3]));
                ap[kp][0] = *(uint32_t*)&t0;
                ap[kp][1] = *(uint32_t*)&t1;
                ap[kp][2] = *(uint32_t*)&t2;
                ap[kp][3] = *(uint32_t*)&t3;
            }

            // ---- O += P V  (trans-ldmatrix: n-tile0=(r0,r2), n-tile1=(r1,r3)) ----
            #pragma unroll
            for (int kp = 0; kp < 4; kp++) {
                uint32_t bv[4][4];
                #pragma unroll
                for (int pd = 0; pd < 4; pd++) {
                    const int row = kp * 16 + (lane & 7) + ((lane >> 4) << 3);
                    const int col = pd * 16 + (((lane >> 3) & 1) << 3);
                    ldsm4t(bv[pd], sV + (uint32_t)(row * SV + col) * 2);
                }
                #pragma unroll
                for (int pd = 0; pd < 4; pd++) {
                    mma_f16(o[2 * pd],     ap[kp], bv[pd][0], bv[pd][2]);
                    mma_f16(o[2 * pd + 1], ap[kp], bv[pd][1], bv[pd][3]);
                }
            }
        }
        __syncthreads();
    }

    // ---- epilogue: normalize + fp16 ----
    float inv[2];
    #pragma unroll
    for (int r = 0; r < 2; r++) {
        float ls = lr[r];
        ls += __shfl_xor_sync(0xFFFFFFFFu, ls, 1);
        ls += __shfl_xor_sync(0xFFFFFFFFu, ls, 2);
        inv[r] = 1.0f / ls;
    }
    #pragma unroll
    for (int r = 0; r < 2; r++) {
        const int trow = qt * AQT + wid * 16 + (lane >> 2) + 8 * r;
        const size_t rowoff = (size_t)(b * SEQT + trow) * EMB + h * HDIM;
        #pragma unroll
        for (int nj = 0; nj < 8; nj++) {
            const int col = nj * 8 + 2 * (lane & 3);
            *(__half2*)&outh[rowoff + col] =
                __floats2half2_rn(o[nj][2 * r] * inv[r], o[nj][2 * r + 1] * inv[r]);
        }
    }
}

// ---------------------------------------------------------------------------
// Launch sequence
// ---------------------------------------------------------------------------
extern "C" void kernel_launch(void* const* d_in, const int* in_sizes, int n_in,
                              void* d_out, int out_size)
{
    const float* x  = (const float*)d_in[0];
    const float* W1 = (const float*)d_in[1];
    const float* W2 = (const float*)d_in[2];
    float* out = (float*)d_out;

    void *p_x16, *p_w1, *p_w2, *p_ah, *p_qh, *p_kh, *p_vh;
    cudaGetSymbolAddress(&p_x16, g_x16);
    cudaGetSymbolAddress(&p_w1, g_w1); cudaGetSymbolAddress(&p_w2, g_w2);
    cudaGetSymbolAddress(&p_ah, g_ah);
    cudaGetSymbolAddress(&p_qh, g_qh); cudaGetSymbolAddress(&p_kh, g_kh);
    cudaGetSymbolAddress(&p_vh, g_vh);

    cudaFuncSetAttribute(gemm_f16<0>, cudaFuncAttributeMaxDynamicSharedMemorySize, GEMM_SMEM);
    cudaFuncSetAttribute(gemm_f16<2>, cudaFuncAttributeMaxDynamicSharedMemorySize, GEMM_SMEM);
    cudaFuncSetAttribute(attn_mma,    cudaFuncAttributeMaxDynamicSharedMemorySize, ATTN_SMEM);

    // conversions
    convert_f16<<<(MROWS * KDIM / 4 + 255) / 256, 256>>>(x,  (__half*)p_x16, MROWS * KDIM / 4);
    convert_f16<<<(E3 * KDIM / 4 + 255) / 256, 256>>>(W1, (__half*)p_w1, E3 * KDIM / 4);
    convert_f16<<<(EMB * KDIM / 4 + 255) / 256, 256>>>(W2, (__half*)p_w2, EMB * KDIM / 4);

    // qkv = x @ W1^T with fused RoPE + repack epilogue
    {
        dim3 g(E3 / GBN, MROWS / GBM);
        gemm_f16<2><<<g, 256, GEMM_SMEM>>>(
            (const __half*)p_x16, (const __half*)p_w1, nullptr, E3,
            (__half*)p_qh, (__half*)p_kh, (__half*)p_vh);
    }

    // attention -> fp16
    {
        dim3 ga(SEQT / AQT, BATCH * NHEAD);
        attn_mma<<<ga, 256, ATTN_SMEM>>>((const __half*)p_qh, (const __half*)p_kh,
                                         (const __half*)p_vh, (__half*)p_ah);
    }

    // out = att @ W2^T  (fp32 out, single pass)
    {
        dim3 g(EMB / GBN, MROWS / GBM);
        gemm_f16<0><<<g, 256, GEMM_SMEM>>>(
            (const __half*)p_ah, (const __half*)p_w2, out, EMB,
            nullptr, nullptr, nullptr);
    }
}

// round 11
// speedup vs baseline: 7.9235x; 1.0401x over previous
#include <cuda_runtime.h>
#include <cuda_fp16.h>
#include <math.h>
#include <stdint.h>

// ---------------------------------------------------------------------------
// Problem constants
// ---------------------------------------------------------------------------
#define BATCH 2
#define SEQT  2048
#define EMB   1024
#define NHEAD 16
#define HDIM  64
#define E3    3072
#define MROWS (BATCH*SEQT)   // 4096
#define KDIM  1024

#define NSM   148
#define PGRID (2 * NSM)      // persistent grid (2 CTAs/SM)

// ---------------------------------------------------------------------------
// Scratch (__device__ globals; no runtime allocation)
// ---------------------------------------------------------------------------
__device__ __half g_x16[(size_t)MROWS * KDIM];               // x fp16
__device__ __half g_w1[(size_t)E3 * KDIM];                   // W1 fp16
__device__ __half g_w2[(size_t)EMB * KDIM];                  // W2 fp16
__device__ __half g_ah[(size_t)MROWS * KDIM];                // attn out
__device__ __half g_qh[(size_t)BATCH * NHEAD * SEQT * HDIM]; // q (scaled, rope)
__device__ __half g_kh[(size_t)BATCH * NHEAD * SEQT * HDIM]; // k (rope)
__device__ __half g_vh[(size_t)BATCH * NHEAD * SEQT * HDIM]; // v

#define QSCALE 0.18033688011112042f   // 0.125 * log2(e)
#define LOG2_10000_OVER32 (13.287712379549449f / 32.0f)

// ---------------------------------------------------------------------------
// Helpers
// ---------------------------------------------------------------------------
__device__ __forceinline__ uint32_t smem_u32(const void* p) {
    uint32_t a;
    asm("{ .reg .u64 t; cvta.to.shared.u64 t, %1; cvt.u32.u64 %0, t; }" : "=r"(a) : "l"(p));
    return a;
}
__device__ __forceinline__ void cp_async16(uint32_t dst, const void* src) {
    asm volatile("cp.async.cg.shared.global [%0], [%1], 16;" :: "r"(dst), "l"(src));
}
__device__ __forceinline__ void cp_commit() {
    asm volatile("cp.async.commit_group;" ::: "memory");
}
template <int N> __device__ __forceinline__ void cp_wait() {
    asm volatile("cp.async.wait_group %0;" :: "n"(N) : "memory");
}
__device__ __forceinline__ void ldsm4(uint32_t* r, uint32_t addr) {
    asm volatile("ldmatrix.sync.aligned.m8n8.x4.shared.b16 {%0,%1,%2,%3}, [%4];"
        : "=r"(r[0]), "=r"(r[1]), "=r"(r[2]), "=r"(r[3]) : "r"(addr));
}
__device__ __forceinline__ void ldsm4t(uint32_t* r, uint32_t addr) {
    asm volatile("ldmatrix.sync.aligned.m8n8.x4.trans.shared.b16 {%0,%1,%2,%3}, [%4];"
        : "=r"(r[0]), "=r"(r[1]), "=r"(r[2]), "=r"(r[3]) : "r"(addr));
}
__device__ __forceinline__ void mma_f16(float* c, const uint32_t* a, uint32_t b0, uint32_t b1) {
    asm volatile(
        "mma.sync.aligned.m16n8k16.row.col.f32.f16.f16.f32 "
        "{%0,%1,%2,%3}, {%4,%5,%6,%7}, {%8,%9}, {%0,%1,%2,%3};"
        : "+f"(c[0]), "+f"(c[1]), "+f"(c[2]), "+f"(c[3])
        : "r"(a[0]), "r"(a[1]), "r"(a[2]), "r"(a[3]), "r"(b0), "r"(b1));
}

// ---------------------------------------------------------------------------
// Conversions
// ---------------------------------------------------------------------------
__global__ void convert_f16(const float* __restrict__ src,
                            __half* __restrict__ dst, int n4)
{
    int i = blockIdx.x * blockDim.x + threadIdx.x;
    if (i >= n4) return;
    float4 v = ((const float4*)src)[i];
    __half2* dp = (__half2*)dst;
    dp[2 * i]     = __floats2half2_rn(v.x, v.y);
    dp[2 * i + 1] = __floats2half2_rn(v.z, v.w);
}

// ---------------------------------------------------------------------------
// fp16 mma GEMM, persistent tiles. C[M,N] = A[M,K] @ B[N,K]^T.
// MODE 0: fp32 C out.  MODE 2: fused RoPE+repack epilogue to qh/kh/vh.
// 128x128x64 tiles, 256 threads (8 warps 4m x 2n), 3-stage cp.async ring.
// ---------------------------------------------------------------------------
#define GBM 128
#define GBN 128
#define GBK 64
#define GSK 72                        // padded smem stride (halves)
#define GMAT (GBM * GSK)              // 9216 halves per matrix tile
#define GSTAGE (2 * GMAT * 2)         // A,B per stage = 36864 bytes
#define GEMM_SMEM (3 * GSTAGE)        // 110592 bytes
#define NCH (KDIM / GBK)              // 16

__device__ __forceinline__ void g2_load(
    uint32_t s0, int tid, int kc, int m0, int n0,
    const __half* __restrict__ A, const __half* __restrict__ B)
{
    const __half* a0 = A + (size_t)m0 * KDIM + kc * GBK;
    const __half* b0 = B + (size_t)n0 * KDIM + kc * GBK;
    // per matrix: 128 rows x 8 chunks(16B) = 1024 chunks; 256 thr -> 4 each
    #pragma unroll
    for (int it = 0; it < 4; it++) {
        const int jj = tid + it * 256;      // 0..1023
        const int row = jj >> 3;
        const int c = jj & 7;
        const uint32_t d = s0 + (uint32_t)(row * GSK + c * 8) * 2;
        const size_t goff = (size_t)row * KDIM + c * 8;
        cp_async16(d, a0 + goff);
        cp_async16(d + GMAT * 2, b0 + goff);
    }
    cp_commit();
}

template <int MODE>
__global__ void __launch_bounds__(256, 2)
gemm_f16(const __half* __restrict__ A, const __half* __restrict__ B,
         float* __restrict__ C, int N, int numTiles,
         __half* __restrict__ qh, __half* __restrict__ kh, __half* __restrict__ vh)
{
    extern __shared__ char smem[];
    const uint32_t sb = smem_u32(smem);
    const int tid = threadIdx.x;
    const int wid = tid >> 5;
    const int lane = tid & 31;
    const int wm = wid >> 1;    // 0..3
    const int wn = wid & 1;     // 0..1
    const int ntiles_n = N / GBN;

    // lane-dependent RoPE inv-freqs (MODE 2 only; constant across tiles)
    float invf[8];
    if (MODE == 2) {
        #pragma unroll
        for (int p = 0; p < 4; p++) {
            const int j0 = p * 8 + 2 * (lane & 3);
            invf[2 * p]     = exp2f(-(float)j0 * LOG2_10000_OVER32);
            invf[2 * p + 1] = exp2f(-(float)(j0 + 1) * LOG2_10000_OVER32);
        }
    }

    for (int t = blockIdx.x; t < numTiles; t += gridDim.x) {
        const int m0 = (t / ntiles_n) * GBM;
        const int n0 = (t % ntiles_n) * GBN;

        float acc[2][8][4];
        #pragma unroll
        for (int i = 0; i < 2; i++)
            #pragma unroll
            for (int j = 0; j < 8; j++)
                #pragma unroll
                for (int k = 0; k < 4; k++) acc[i][j][k] = 0.f;

        g2_load(sb,          tid, 0, m0, n0, A, B);
        g2_load(sb + GSTAGE, tid, 1, m0, n0, A, B);

        for (int c = 0; c < NCH; c++) {
            if (c + 1 < NCH) cp_wait<1>(); else cp_wait<0>();
            __syncthreads();

            const uint32_t scur = sb + (uint32_t)(c % 3) * GSTAGE;
            const uint32_t sA = scur;
            const uint32_t sB = scur + GMAT * 2;

            #pragma unroll
            for (int ks = 0; ks < 4; ks++) {
                const int k0 = ks * 16;
                uint32_t aF[2][4];
                #pragma unroll
                for (int mi = 0; mi < 2; mi++) {
                    const int row = wm * 32 + mi * 16 + (lane & 15);
                    const int col = k0 + ((lane >> 4) << 3);
                    ldsm4(aF[mi], sA + (uint32_t)(row * GSK + col) * 2);
                }
                #pragma unroll
                for (int p = 0; p < 4; p++) {
                    uint32_t bb[4];
                    const int row = wn * 64 + p * 16 + (lane & 7) + ((lane >> 4) << 3);
                    const int col = k0 + (((lane >> 3) & 1) << 3);
                    ldsm4(bb, sB + (uint32_t)(row * GSK + col) * 2);
                    #pragma unroll
                    for (int mi = 0; mi < 2; mi++) {
                        mma_f16(acc[mi][2 * p],     aF[mi], bb[0], bb[1]);
                        mma_f16(acc[mi][2 * p + 1], aF[mi], bb[2], bb[3]);
                    }
                }
            }
            if (c + 2 < NCH)
                g2_load(sb + (uint32_t)((c + 2) % 3) * GSTAGE, tid, c + 2, m0, n0, A, B);
        }

        if (MODE == 0) {
            // fp32 epilogue
            #pragma unroll
            for (int mi = 0; mi < 2; mi++) {
                const int r0 = m0 + wm * 32 + mi * 16 + (lane >> 2);
                #pragma unroll
                for (int nj = 0; nj < 8; nj++) {
                    const int col = n0 + wn * 64 + nj * 8 + 2 * (lane & 3);
                    *(float2*)&C[(size_t)r0 * N + col] =
                        make_float2(acc[mi][nj][0], acc[mi][nj][1]);
                    *(float2*)&C[(size_t)(r0 + 8) * N + col] =
                        make_float2(acc[mi][nj][2], acc[mi][nj][3]);
                }
            }
        } else {
            // fused RoPE + repack epilogue.
            // Warp owns cols [cbase, cbase+64) = exactly one head of q, k, or v.
            const int cbase = n0 + wn * 64;
            const int sec = cbase >> 10;            // 0=q 1=k 2=v
            const int hd  = (cbase & 1023) >> 6;
            __half* dst = (sec == 0) ? qh : (sec == 1) ? kh : vh;

            #pragma unroll
            for (int mi = 0; mi < 2; mi++) {
                #pragma unroll
                for (int rr = 0; rr < 2; rr++) {
                    const int r = m0 + wm * 32 + mi * 16 + (lane >> 2) + rr * 8;
                    const int bb = r >> 11;
                    const int tt = r & 2047;
                    __half* drow = dst + ((size_t)((bb * NHEAD + hd) * SEQT + tt)) * HDIM;
                    if (sec == 2) {
                        #pragma unroll
                        for (int nj = 0; nj < 8; nj++) {
                            const int j0 = nj * 8 + 2 * (lane & 3);
                            *(__half2*)&drow[j0] =
                                __floats2half2_rn(acc[mi][nj][2 * rr], acc[mi][nj][2 * rr + 1]);
                        }
                    } else {
                        const float qs = (sec == 0) ? QSCALE : 1.0f;
                        const float tf = (float)tt;
                        #pragma unroll
                        for (int p = 0; p < 4; p++) {
                            const int j0 = p * 8 + 2 * (lane & 3);
                            const float a0 = acc[mi][p][2 * rr];
                            const float a1 = acc[mi][p][2 * rr + 1];
                            const float b0 = acc[mi][p + 4][2 * rr];
                            const float b1 = acc[mi][p + 4][2 * rr + 1];
                            float s0, c0, s1, c1;
                            sincosf(tf * invf[2 * p], &s0, &c0);
                            sincosf(tf * invf[2 * p + 1], &s1, &c1);
                            *(__half2*)&drow[j0] =
                                __floats2half2_rn(qs * (a0 * c0 - b0 * s0),
                                                  qs * (a1 * c1 - b1 * s1));
                            *(__half2*)&drow[j0 + 32] =
                                __floats2half2_rn(qs * (b0 * c0 + a0 * s0),
                                                  qs * (b1 * c1 + a1 * s1));
                        }
                    }
                }
            }
        }
        // smem reuse barrier before next tile's loads
        __syncthreads();
    }
}

// ---------------------------------------------------------------------------
// fp16 mma causal flash attention. 256 threads (8 warps), 128 queries per
// block. K-tile = 64, double-buffered cp.async. exp2-domain softmax.
// Fully-masked warp tiles skip compute. Dynamic smem 55296 B.
// Output fp16 into [b][t][h*64+d].
// ---------------------------------------------------------------------------
#define SV 72   // smem row stride (halves)
#define AQT 128
#define ATTN_SQ_OFF 0
#define ATTN_SK_OFF (AQT * SV * 2)                    // 18432
#define ATTN_SV_OFF (ATTN_SK_OFF + 2 * 64 * SV * 2)   // 36864
#define ATTN_SMEM   (ATTN_SV_OFF + 2 * 64 * SV * 2)   // 55296

__global__ void __launch_bounds__(256, 2) attn_mma(
    const __half* __restrict__ qh, const __half* __restrict__ kh,
    const __half* __restrict__ vh, __half* __restrict__ outh)
{
    extern __shared__ char asmem[];
    const uint32_t sbase = smem_u32(asmem);
    const uint32_t sQ = sbase + ATTN_SQ_OFF;
    const uint32_t sKb[2] = { sbase + ATTN_SK_OFF, sbase + ATTN_SK_OFF + 64 * SV * 2 };
    const uint32_t sVb[2] = { sbase + ATTN_SV_OFF, sbase + ATTN_SV_OFF + 64 * SV * 2 };

    const int bh = blockIdx.y;
    const int b = bh >> 4;
    const int h = bh & 15;
    const int qt = (gridDim.x - 1) - blockIdx.x;   // heavy tiles first
    const int tid = threadIdx.x;
    const int wid = tid >> 5;
    const int lane = tid & 31;

    const __half* qg = qh + (size_t)bh * SEQT * HDIM;
    const __half* kg = kh + (size_t)bh * SEQT * HDIM;
    const __half* vg = vh + (size_t)bh * SEQT * HDIM;

    // Load Q tile: 128 rows x 8 chunks = 1024 chunks, 4/thread
    #pragma unroll
    for (int i = 0; i < 4; i++) {
        const int ch = tid + i * 256;
        const int row = ch >> 3;
        const int c = ch & 7;
        cp_async16(sQ + (uint32_t)(row * SV + c * 8) * 2,
                   qg + (size_t)(qt * AQT + row) * HDIM + c * 8);
    }
    cp_commit();

    // Prefetch K/V tile 0 (512 chunks each, 2/thread)
    {
        #pragma unroll
        for (int i = 0; i < 2; i++) {
            const int ch = tid + i * 256;
            const int row = ch >> 3;
            const int c = ch & 7;
            const uint32_t d = (uint32_t)(row * SV + c * 8) * 2;
            const size_t goff = (size_t)row * HDIM + c * 8;
            cp_async16(sKb[0] + d, kg + goff);
            cp_async16(sVb[0] + d, vg + goff);
        }
        cp_commit();
    }

    cp_wait<1>();   // Q ready
    __syncthreads();

    uint32_t aq[4][4];
    #pragma unroll
    for (int ks = 0; ks < 4; ks++) {
        const int row = wid * 16 + (lane & 15);
        const int col = ks * 16 + ((lane >> 4) << 3);
        ldsm4(aq[ks], sQ + (uint32_t)(row * SV + col) * 2);
    }

    float o[8][4];
    #pragma unroll
    for (int j = 0; j < 8; j++)
        #pragma unroll
        for (int k = 0; k < 4; k++) o[j][k] = 0.f;
    float mr[2] = {-1e30f, -1e30f};
    float lr[2] = {0.f, 0.f};

    const int q0g = qt * AQT + wid * 16;       // first query row of this warp
    const int NKT = 2 * qt + 2;                // k-tiles to visit

    for (int kt = 0; kt < NKT; kt++) {
        const int cb = kt & 1;
        if (kt + 1 < NKT) {
            const uint32_t sKn = sKb[1 - cb];
            const uint32_t sVn = sVb[1 - cb];
            #pragma unroll
            for (int i = 0; i < 2; i++) {
                const int ch = tid + i * 256;
                const int row = ch >> 3;
                const int c = ch & 7;
                const uint32_t d = (uint32_t)(row * SV + c * 8) * 2;
                const size_t goff = (size_t)((kt + 1) * 64 + row) * HDIM + c * 8;
                cp_async16(sKn + d, kg + goff);
                cp_async16(sVn + d, vg + goff);
            }
            cp_commit();
            cp_wait<1>();
        } else {
            cp_wait<0>();
        }
        __syncthreads();

        const int kbase = kt * 64;
        const bool active = (kbase <= q0g + 15);   // any unmasked key for warp?
        if (active) {
            const uint32_t sK = sKb[cb];
            const uint32_t sV = sVb[cb];

            // ---- S = Q K^T ----
            float sacc[8][4];
            #pragma unroll
            for (int j = 0; j < 8; j++)
                #pragma unroll
                for (int k = 0; k < 4; k++) sacc[j][k] = 0.f;

            #pragma unroll
            for (int ks = 0; ks < 4; ks++) {
                uint32_t bk[4][4];
                #pragma unroll
                for (int p = 0; p < 4; p++) {
                    const int row = p * 16 + (lane & 7) + ((lane >> 4) << 3);
                    const int col = ks * 16 + (((lane >> 3) & 1) << 3);
                    ldsm4(bk[p], sK + (uint32_t)(row * SV + col) * 2);
                }
                #pragma unroll
                for (int p = 0; p < 4; p++) {
                    mma_f16(sacc[2 * p],     aq[ks], bk[p][0], bk[p][1]);
                    mma_f16(sacc[2 * p + 1], aq[ks], bk[p][2], bk[p][3]);
                }
            }

            // ---- causal mask (possibly-diagonal tiles) ----
            if (kbase + 63 > q0g) {
                const int qg0 = q0g + (lane >> 2);   // r=0 global query row
                #pragma unroll
                for (int nj = 0; nj < 8; nj++) {
                    const int col = kbase + nj * 8 + 2 * (lane & 3);
                    if (col > qg0)         sacc[nj][0] = -1e30f;
                    if (col + 1 > qg0)     sacc[nj][1] = -1e30f;
                    if (col > qg0 + 8)     sacc[nj][2] = -1e30f;
                    if (col + 1 > qg0 + 8) sacc[nj][3] = -1e30f;
                }
            }

            // ---- online softmax (exp2 domain) ----
            #pragma unroll
            for (int r = 0; r < 2; r++) {
                float mt = -1e30f;
                #pragma unroll
                for (int nj = 0; nj < 8; nj++)
                    mt = fmaxf(mt, fmaxf(sacc[nj][2 * r], sacc[nj][2 * r + 1]));
                mt = fmaxf(mt, __shfl_xor_sync(0xFFFFFFFFu, mt, 1));
                mt = fmaxf(mt, __shfl_xor_sync(0xFFFFFFFFu, mt, 2));
                const float mnew = fmaxf(mr[r], mt);
                const float alpha = exp2f(mr[r] - mnew);
                mr[r] = mnew;
                lr[r] *= alpha;
                #pragma unroll
                for (int nj = 0; nj < 8; nj++) {
                    o[nj][2 * r] *= alpha;
                    o[nj][2 * r + 1] *= alpha;
                }
                float psum = 0.f;
                #pragma unroll
                for (int nj = 0; nj < 8; nj++) {
                    const float p0 = exp2f(sacc[nj][2 * r] - mnew);
                    const float p1 = exp2f(sacc[nj][2 * r + 1] - mnew);
                    sacc[nj][2 * r] = p0;
                    sacc[nj][2 * r + 1] = p1;
                    psum += p0 + p1;
                }
                lr[r] += psum;
            }

            // ---- P fragments ----
            uint32_t ap[4][4];
            #pragma unroll
            for (int kp = 0; kp < 4; kp++) {
                const int nj = 2 * kp;
                __half2 t0 = __float22half2_rn(make_float2(sacc[nj][0], sacc[nj][1]));
                __half2 t1 = __float22half2_rn(make_float2(sacc[nj][2], sacc[nj][3]));
                __half2 t2 = __float22half2_rn(make_float2(sacc[nj + 1][0], sacc[nj + 1][1]));
                __half2 t3 = __float22half2_rn(make_float2(sacc[nj + 1][2], sacc[nj + 1][3]));
                ap[kp][0] = *(uint32_t*)&t0;
                ap[kp][1] = *(uint32_t*)&t1;
                ap[kp][2] = *(uint32_t*)&t2;
                ap[kp][3] = *(uint32_t*)&t3;
            }

            // ---- O += P V  (trans-ldmatrix: n-tile0=(r0,r2), n-tile1=(r1,r3)) ----
            #pragma unroll
            for (int kp = 0; kp < 4; kp++) {
                uint32_t bv[4][4];
                #pragma unroll
                for (int pd = 0; pd < 4; pd++) {
                    const int row = kp * 16 + (lane & 7) + ((lane >> 4) << 3);
                    const int col = pd * 16 + (((lane >> 3) & 1) << 3);
                    ldsm4t(bv[pd], sV + (uint32_t)(row * SV + col) * 2);
                }
                #pragma unroll
                for (int pd = 0; pd < 4; pd++) {
                    mma_f16(o[2 * pd],     ap[kp], bv[pd][0], bv[pd][2]);
                    mma_f16(o[2 * pd + 1], ap[kp], bv[pd][1], bv[pd][3]);
                }
            }
        }
        __syncthreads();
    }

    // ---- epilogue: normalize + fp16 ----
    float inv[2];
    #pragma unroll
    for (int r = 0; r < 2; r++) {
        float ls = lr[r];
        ls += __shfl_xor_sync(0xFFFFFFFFu, ls, 1);
        ls += __shfl_xor_sync(0xFFFFFFFFu, ls, 2);
        inv[r] = 1.0f / ls;
    }
    #pragma unroll
    for (int r = 0; r < 2; r++) {
        const int trow = qt * AQT + wid * 16 + (lane >> 2) + 8 * r;
        const size_t rowoff = (size_t)(b * SEQT + trow) * EMB + h * HDIM;
        #pragma unroll
        for (int nj = 0; nj < 8; nj++) {
            const int col = nj * 8 + 2 * (lane & 3);
            *(__half2*)&outh[rowoff + col] =
                __floats2half2_rn(o[nj][2 * r] * inv[r], o[nj][2 * r + 1] * inv[r]);
        }
    }
}

// ---------------------------------------------------------------------------
// Launch sequence
// ---------------------------------------------------------------------------
extern "C" void kernel_launch(void* const* d_in, const int* in_sizes, int n_in,
                              void* d_out, int out_size)
{
    const float* x  = (const float*)d_in[0];
    const float* W1 = (const float*)d_in[1];
    const float* W2 = (const float*)d_in[2];
    float* out = (float*)d_out;

    void *p_x16, *p_w1, *p_w2, *p_ah, *p_qh, *p_kh, *p_vh;
    cudaGetSymbolAddress(&p_x16, g_x16);
    cudaGetSymbolAddress(&p_w1, g_w1); cudaGetSymbolAddress(&p_w2, g_w2);
    cudaGetSymbolAddress(&p_ah, g_ah);
    cudaGetSymbolAddress(&p_qh, g_qh); cudaGetSymbolAddress(&p_kh, g_kh);
    cudaGetSymbolAddress(&p_vh, g_vh);

    cudaFuncSetAttribute(gemm_f16<0>, cudaFuncAttributeMaxDynamicSharedMemorySize, GEMM_SMEM);
    cudaFuncSetAttribute(gemm_f16<2>, cudaFuncAttributeMaxDynamicSharedMemorySize, GEMM_SMEM);
    cudaFuncSetAttribute(attn_mma,    cudaFuncAttributeMaxDynamicSharedMemorySize, ATTN_SMEM);

    // conversions
    convert_f16<<<(MROWS * KDIM / 4 + 255) / 256, 256>>>(x,  (__half*)p_x16, MROWS * KDIM / 4);
    convert_f16<<<(E3 * KDIM / 4 + 255) / 256, 256>>>(W1, (__half*)p_w1, E3 * KDIM / 4);
    convert_f16<<<(EMB * KDIM / 4 + 255) / 256, 256>>>(W2, (__half*)p_w2, EMB * KDIM / 4);

    // qkv = x @ W1^T with fused RoPE + repack epilogue (persistent tiles)
    {
        const int tiles = (MROWS / GBM) * (E3 / GBN);   // 768
        const int grid = tiles < PGRID ? tiles : PGRID;
        gemm_f16<2><<<grid, 256, GEMM_SMEM>>>(
            (const __half*)p_x16, (const __half*)p_w1, nullptr, E3, tiles,
            (__half*)p_qh, (__half*)p_kh, (__half*)p_vh);
    }

    // attention -> fp16
    {
        dim3 ga(SEQT / AQT, BATCH * NHEAD);
        attn_mma<<<ga, 256, ATTN_SMEM>>>((const __half*)p_qh, (const __half*)p_kh,
                                         (const __half*)p_vh, (__half*)p_ah);
    }

    // out = att @ W2^T  (fp32 out, single pass, persistent tiles)
    {
        const int tiles = (MROWS / GBM) * (EMB / GBN);  // 256
        const int grid = tiles < PGRID ? tiles : PGRID;
        gemm_f16<0><<<grid, 256, GEMM_SMEM>>>(
            (const __half*)p_ah, (const __half*)p_w2, out, EMB, tiles,
            nullptr, nullptr, nullptr);
    }
}

// round 14
// speedup vs baseline: 8.1223x; 1.0251x over previous
#include <cuda_runtime.h>
#include <cuda_fp16.h>
#include <math.h>
#include <stdint.h>

// ---------------------------------------------------------------------------
// Problem constants
// ---------------------------------------------------------------------------
#define BATCH 2
#define SEQT  2048
#define EMB   1024
#define NHEAD 16
#define HDIM  64
#define E3    3072
#define MROWS (BATCH*SEQT)   // 4096
#define KDIM  1024

#define NSM   148
#define PGRID (2 * NSM)      // persistent grid (2 CTAs/SM)

// ---------------------------------------------------------------------------
// Scratch (__device__ globals; no runtime allocation)
// ---------------------------------------------------------------------------
__device__ __half g_x16[(size_t)MROWS * KDIM];               // x fp16
__device__ __half g_w1[(size_t)E3 * KDIM];                   // W1 fp16
__device__ __half g_w2[(size_t)EMB * KDIM];                  // W2 fp16
__device__ __half g_ah[(size_t)MROWS * KDIM];                // attn out
__device__ __half g_qh[(size_t)BATCH * NHEAD * SEQT * HDIM]; // q (scaled, rope)
__device__ __half g_kh[(size_t)BATCH * NHEAD * SEQT * HDIM]; // k (rope)
__device__ __half g_vh[(size_t)BATCH * NHEAD * SEQT * HDIM]; // v

#define QSCALE 0.18033688011112042f   // 0.125 * log2(e)
#define LOG2_10000_OVER32 (13.287712379549449f / 32.0f)

// ---------------------------------------------------------------------------
// Helpers
// ---------------------------------------------------------------------------
__device__ __forceinline__ uint32_t smem_u32(const void* p) {
    uint32_t a;
    asm("{ .reg .u64 t; cvta.to.shared.u64 t, %1; cvt.u32.u64 %0, t; }" : "=r"(a) : "l"(p));
    return a;
}
__device__ __forceinline__ void cp_async16(uint32_t dst, const void* src) {
    asm volatile("cp.async.cg.shared.global [%0], [%1], 16;" :: "r"(dst), "l"(src));
}
__device__ __forceinline__ void cp_commit() {
    asm volatile("cp.async.commit_group;" ::: "memory");
}
template <int N> __device__ __forceinline__ void cp_wait() {
    asm volatile("cp.async.wait_group %0;" :: "n"(N) : "memory");
}
__device__ __forceinline__ void ldsm4(uint32_t* r, uint32_t addr) {
    asm volatile("ldmatrix.sync.aligned.m8n8.x4.shared.b16 {%0,%1,%2,%3}, [%4];"
        : "=r"(r[0]), "=r"(r[1]), "=r"(r[2]), "=r"(r[3]) : "r"(addr));
}
__device__ __forceinline__ void ldsm4t(uint32_t* r, uint32_t addr) {
    asm volatile("ldmatrix.sync.aligned.m8n8.x4.trans.shared.b16 {%0,%1,%2,%3}, [%4];"
        : "=r"(r[0]), "=r"(r[1]), "=r"(r[2]), "=r"(r[3]) : "r"(addr));
}
__device__ __forceinline__ void mma_f16(float* c, const uint32_t* a, uint32_t b0, uint32_t b1) {
    asm volatile(
        "mma.sync.aligned.m16n8k16.row.col.f32.f16.f16.f32 "
        "{%0,%1,%2,%3}, {%4,%5,%6,%7}, {%8,%9}, {%0,%1,%2,%3};"
        : "+f"(c[0]), "+f"(c[1]), "+f"(c[2]), "+f"(c[3])
        : "r"(a[0]), "r"(a[1]), "r"(a[2]), "r"(a[3]), "r"(b0), "r"(b1));
}

// ---------------------------------------------------------------------------
// Merged conversion: x, W1, W2 -> fp16 in ONE launch (range dispatch).
// ---------------------------------------------------------------------------
#define XN4  (MROWS * KDIM / 4)          // 1048576
#define W1N4 (E3 * KDIM / 4)             // 786432
#define W2N4 (EMB * KDIM / 4)            // 262144
#define ALLN4 (XN4 + W1N4 + W2N4)        // 2097152

__global__ void convert_all(const float* __restrict__ x, const float* __restrict__ W1,
                            const float* __restrict__ W2,
                            __half* __restrict__ x16, __half* __restrict__ w1,
                            __half* __restrict__ w2)
{
    int i = blockIdx.x * blockDim.x + threadIdx.x;
    const float* src;
    __half* dst;
    int j;
    if (i < XN4) {
        src = x; dst = x16; j = i;
    } else if (i < XN4 + W1N4) {
        src = W1; dst = w1; j = i - XN4;
    } else if (i < ALLN4) {
        src = W2; dst = w2; j = i - XN4 - W1N4;
    } else {
        return;
    }
    float4 v = ((const float4*)src)[j];
    __half2* dp = (__half2*)dst;
    dp[2 * j]     = __floats2half2_rn(v.x, v.y);
    dp[2 * j + 1] = __floats2half2_rn(v.z, v.w);
}

// ---------------------------------------------------------------------------
// fp16 mma GEMM, persistent tiles. C[M,N] = A[M,K] @ B[N,K]^T.
// MODE 0: fp32 C out.  MODE 2: fused RoPE+repack epilogue to qh/kh/vh.
// 128x128x64 tiles, 256 threads (8 warps 4m x 2n), 3-stage cp.async ring.
// Inner loop: ALL fragment ldsm hoisted before the MMA burst per ks-step.
// ---------------------------------------------------------------------------
#define GBM 128
#define GBN 128
#define GBK 64
#define GSK 72                        // padded smem stride (halves)
#define GMAT (GBM * GSK)              // 9216 halves per matrix tile
#define GSTAGE (2 * GMAT * 2)         // A,B per stage = 36864 bytes
#define GEMM_SMEM (3 * GSTAGE)        // 110592 bytes
#define NCH (KDIM / GBK)              // 16

__device__ __forceinline__ void g2_load(
    uint32_t s0, int tid, int kc, int m0, int n0,
    const __half* __restrict__ A, const __half* __restrict__ B)
{
    const __half* a0 = A + (size_t)m0 * KDIM + kc * GBK;
    const __half* b0 = B + (size_t)n0 * KDIM + kc * GBK;
    #pragma unroll
    for (int it = 0; it < 4; it++) {
        const int jj = tid + it * 256;      // 0..1023
        const int row = jj >> 3;
        const int c = jj & 7;
        const uint32_t d = s0 + (uint32_t)(row * GSK + c * 8) * 2;
        const size_t goff = (size_t)row * KDIM + c * 8;
        cp_async16(d, a0 + goff);
        cp_async16(d + GMAT * 2, b0 + goff);
    }
    cp_commit();
}

template <int MODE>
__global__ void __launch_bounds__(256, 2)
gemm_f16(const __half* __restrict__ A, const __half* __restrict__ B,
         float* __restrict__ C, int N, int numTiles,
         __half* __restrict__ qh, __half* __restrict__ kh, __half* __restrict__ vh)
{
    extern __shared__ char smem[];
    const uint32_t sb = smem_u32(smem);
    const int tid = threadIdx.x;
    const int wid = tid >> 5;
    const int lane = tid & 31;
    const int wm = wid >> 1;    // 0..3
    const int wn = wid & 1;     // 0..1
    const int ntiles_n = N / GBN;

    float invf[8];
    if (MODE == 2) {
        #pragma unroll
        for (int p = 0; p < 4; p++) {
            const int j0 = p * 8 + 2 * (lane & 3);
            invf[2 * p]     = exp2f(-(float)j0 * LOG2_10000_OVER32);
            invf[2 * p + 1] = exp2f(-(float)(j0 + 1) * LOG2_10000_OVER32);
        }
    }

    for (int t = blockIdx.x; t < numTiles; t += gridDim.x) {
        const int m0 = (t / ntiles_n) * GBM;
        const int n0 = (t % ntiles_n) * GBN;

        float acc[2][8][4];
        #pragma unroll
        for (int i = 0; i < 2; i++)
            #pragma unroll
            for (int j = 0; j < 8; j++)
                #pragma unroll
                for (int k = 0; k < 4; k++) acc[i][j][k] = 0.f;

        g2_load(sb,          tid, 0, m0, n0, A, B);
        g2_load(sb + GSTAGE, tid, 1, m0, n0, A, B);

        for (int c = 0; c < NCH; c++) {
            if (c + 1 < NCH) cp_wait<1>(); else cp_wait<0>();
            __syncthreads();

            const uint32_t scur = sb + (uint32_t)(c % 3) * GSTAGE;
            const uint32_t sA = scur;
            const uint32_t sB = scur + GMAT * 2;

            #pragma unroll
            for (int ks = 0; ks < 4; ks++) {
                const int k0 = ks * 16;
                // hoist ALL fragment loads for this ks-step
                uint32_t aF[2][4], bk[4][4];
                #pragma unroll
                for (int mi = 0; mi < 2; mi++) {
                    const int row = wm * 32 + mi * 16 + (lane & 15);
                    const int col = k0 + ((lane >> 4) << 3);
                    ldsm4(aF[mi], sA + (uint32_t)(row * GSK + col) * 2);
                }
                #pragma unroll
                for (int p = 0; p < 4; p++) {
                    const int row = wn * 64 + p * 16 + (lane & 7) + ((lane >> 4) << 3);
                    const int col = k0 + (((lane >> 3) & 1) << 3);
                    ldsm4(bk[p], sB + (uint32_t)(row * GSK + col) * 2);
                }
                // MMA burst (16 independent-target MMAs)
                #pragma unroll
                for (int p = 0; p < 4; p++) {
                    #pragma unroll
                    for (int mi = 0; mi < 2; mi++) {
                        mma_f16(acc[mi][2 * p],     aF[mi], bk[p][0], bk[p][1]);
                        mma_f16(acc[mi][2 * p + 1], aF[mi], bk[p][2], bk[p][3]);
                    }
                }
            }
            if (c + 2 < NCH)
                g2_load(sb + (uint32_t)((c + 2) % 3) * GSTAGE, tid, c + 2, m0, n0, A, B);
        }

        if (MODE == 0) {
            #pragma unroll
            for (int mi = 0; mi < 2; mi++) {
                const int r0 = m0 + wm * 32 + mi * 16 + (lane >> 2);
                #pragma unroll
                for (int nj = 0; nj < 8; nj++) {
                    const int col = n0 + wn * 64 + nj * 8 + 2 * (lane & 3);
                    *(float2*)&C[(size_t)r0 * N + col] =
                        make_float2(acc[mi][nj][0], acc[mi][nj][1]);
                    *(float2*)&C[(size_t)(r0 + 8) * N + col] =
                        make_float2(acc[mi][nj][2], acc[mi][nj][3]);
                }
            }
        } else {
            // fused RoPE + repack epilogue (warp owns one head of q/k/v)
            const int cbase = n0 + wn * 64;
            const int sec = cbase >> 10;            // 0=q 1=k 2=v
            const int hd  = (cbase & 1023) >> 6;
            __half* dst = (sec == 0) ? qh : (sec == 1) ? kh : vh;

            #pragma unroll
            for (int mi = 0; mi < 2; mi++) {
                #pragma unroll
                for (int rr = 0; rr < 2; rr++) {
                    const int r = m0 + wm * 32 + mi * 16 + (lane >> 2) + rr * 8;
                    const int bb = r >> 11;
                    const int tt = r & 2047;
                    __half* drow = dst + ((size_t)((bb * NHEAD + hd) * SEQT + tt)) * HDIM;
                    if (sec == 2) {
                        #pragma unroll
                        for (int nj = 0; nj < 8; nj++) {
                            const int j0 = nj * 8 + 2 * (lane & 3);
                            *(__half2*)&drow[j0] =
                                __floats2half2_rn(acc[mi][nj][2 * rr], acc[mi][nj][2 * rr + 1]);
                        }
                    } else {
                        const float qs = (sec == 0) ? QSCALE : 1.0f;
                        const float tf = (float)tt;
                        #pragma unroll
                        for (int p = 0; p < 4; p++) {
                            const int j0 = p * 8 + 2 * (lane & 3);
                            const float a0 = acc[mi][p][2 * rr];
                            const float a1 = acc[mi][p][2 * rr + 1];
                            const float b0 = acc[mi][p + 4][2 * rr];
                            const float b1 = acc[mi][p + 4][2 * rr + 1];
                            float s0, c0, s1, c1;
                            sincosf(tf * invf[2 * p], &s0, &c0);
                            sincosf(tf * invf[2 * p + 1], &s1, &c1);
                            *(__half2*)&drow[j0] =
                                __floats2half2_rn(qs * (a0 * c0 - b0 * s0),
                                                  qs * (a1 * c1 - b1 * s1));
                            *(__half2*)&drow[j0 + 32] =
                                __floats2half2_rn(qs * (b0 * c0 + a0 * s0),
                                                  qs * (b1 * c1 + a1 * s1));
                        }
                    }
                }
            }
        }
        __syncthreads();
    }
}

// ---------------------------------------------------------------------------
// fp16 mma causal flash attention. 256 threads (8 warps), 128 queries per
// block. K-tile = 64, double-buffered cp.async. exp2-domain softmax.
// Fully-masked warp tiles skip compute. Dynamic smem 55296 B.
// ---------------------------------------------------------------------------
#define SV 72   // smem row stride (halves)
#define AQT 128
#define ATTN_SQ_OFF 0
#define ATTN_SK_OFF (AQT * SV * 2)                    // 18432
#define ATTN_SV_OFF (ATTN_SK_OFF + 2 * 64 * SV * 2)   // 36864
#define ATTN_SMEM   (ATTN_SV_OFF + 2 * 64 * SV * 2)   // 55296

__global__ void __launch_bounds__(256, 2) attn_mma(
    const __half* __restrict__ qh, const __half* __restrict__ kh,
    const __half* __restrict__ vh, __half* __restrict__ outh)
{
    extern __shared__ char asmem[];
    const uint32_t sbase = smem_u32(asmem);
    const uint32_t sQ = sbase + ATTN_SQ_OFF;
    const uint32_t sKb[2] = { sbase + ATTN_SK_OFF, sbase + ATTN_SK_OFF + 64 * SV * 2 };
    const uint32_t sVb[2] = { sbase + ATTN_SV_OFF, sbase + ATTN_SV_OFF + 64 * SV * 2 };

    const int bh = blockIdx.y;
    const int b = bh >> 4;
    const int h = bh & 15;
    const int qt = (gridDim.x - 1) - blockIdx.x;   // heavy tiles first
    const int tid = threadIdx.x;
    const int wid = tid >> 5;
    const int lane = tid & 31;

    const __half* qg = qh + (size_t)bh * SEQT * HDIM;
    const __half* kg = kh + (size_t)bh * SEQT * HDIM;
    const __half* vg = vh + (size_t)bh * SEQT * HDIM;

    #pragma unroll
    for (int i = 0; i < 4; i++) {
        const int ch = tid + i * 256;
        const int row = ch >> 3;
        const int c = ch & 7;
        cp_async16(sQ + (uint32_t)(row * SV + c * 8) * 2,
                   qg + (size_t)(qt * AQT + row) * HDIM + c * 8);
    }
    cp_commit();

    {
        #pragma unroll
        for (int i = 0; i < 2; i++) {
            const int ch = tid + i * 256;
            const int row = ch >> 3;
            const int c = ch & 7;
            const uint32_t d = (uint32_t)(row * SV + c * 8) * 2;
            const size_t goff = (size_t)row * HDIM + c * 8;
            cp_async16(sKb[0] + d, kg + goff);
            cp_async16(sVb[0] + d, vg + goff);
        }
        cp_commit();
    }

    cp_wait<1>();
    __syncthreads();

    uint32_t aq[4][4];
    #pragma unroll
    for (int ks = 0; ks < 4; ks++) {
        const int row = wid * 16 + (lane & 15);
        const int col = ks * 16 + ((lane >> 4) << 3);
        ldsm4(aq[ks], sQ + (uint32_t)(row * SV + col) * 2);
    }

    float o[8][4];
    #pragma unroll
    for (int j = 0; j < 8; j++)
        #pragma unroll
        for (int k = 0; k < 4; k++) o[j][k] = 0.f;
    float mr[2] = {-1e30f, -1e30f};
    float lr[2] = {0.f, 0.f};

    const int q0g = qt * AQT + wid * 16;
    const int NKT = 2 * qt + 2;

    for (int kt = 0; kt < NKT; kt++) {
        const int cb = kt & 1;
        if (kt + 1 < NKT) {
            const uint32_t sKn = sKb[1 - cb];
            const uint32_t sVn = sVb[1 - cb];
            #pragma unroll
            for (int i = 0; i < 2; i++) {
                const int ch = tid + i * 256;
                const int row = ch >> 3;
                const int c = ch & 7;
                const uint32_t d = (uint32_t)(row * SV + c * 8) * 2;
                const size_t goff = (size_t)((kt + 1) * 64 + row) * HDIM + c * 8;
                cp_async16(sKn + d, kg + goff);
                cp_async16(sVn + d, vg + goff);
            }
            cp_commit();
            cp_wait<1>();
        } else {
            cp_wait<0>();
        }
        __syncthreads();

        const int kbase = kt * 64;
        const bool active = (kbase <= q0g + 15);
        if (active) {
            const uint32_t sK = sKb[cb];
            const uint32_t sV = sVb[cb];

            float sacc[8][4];
            #pragma unroll
            for (int j = 0; j < 8; j++)
                #pragma unroll
                for (int k = 0; k < 4; k++) sacc[j][k] = 0.f;

            #pragma unroll
            for (int ks = 0; ks < 4; ks++) {
                uint32_t bk[4][4];
                #pragma unroll
                for (int p = 0; p < 4; p++) {
                    const int row = p * 16 + (lane & 7) + ((lane >> 4) << 3);
                    const int col = ks * 16 + (((lane >> 3) & 1) << 3);
                    ldsm4(bk[p], sK + (uint32_t)(row * SV + col) * 2);
                }
                #pragma unroll
                for (int p = 0; p < 4; p++) {
                    mma_f16(sacc[2 * p],     aq[ks], bk[p][0], bk[p][1]);
                    mma_f16(sacc[2 * p + 1], aq[ks], bk[p][2], bk[p][3]);
                }
            }

            if (kbase + 63 > q0g) {
                const int qg0 = q0g + (lane >> 2);
                #pragma unroll
                for (int nj = 0; nj < 8; nj++) {
                    const int col = kbase + nj * 8 + 2 * (lane & 3);
                    if (col > qg0)         sacc[nj][0] = -1e30f;
                    if (col + 1 > qg0)     sacc[nj][1] = -1e30f;
                    if (col > qg0 + 8)     sacc[nj][2] = -1e30f;
                    if (col + 1 > qg0 + 8) sacc[nj][3] = -1e30f;
                }
            }

            #pragma unroll
            for (int r = 0; r < 2; r++) {
                float mt = -1e30f;
                #pragma unroll
                for (int nj = 0; nj < 8; nj++)
                    mt = fmaxf(mt, fmaxf(sacc[nj][2 * r], sacc[nj][2 * r + 1]));
                mt = fmaxf(mt, __shfl_xor_sync(0xFFFFFFFFu, mt, 1));
                mt = fmaxf(mt, __shfl_xor_sync(0xFFFFFFFFu, mt, 2));
                const float mnew = fmaxf(mr[r], mt);
                const float alpha = exp2f(mr[r] - mnew);
                mr[r] = mnew;
                lr[r] *= alpha;
                #pragma unroll
                for (int nj = 0; nj < 8; nj++) {
                    o[nj][2 * r] *= alpha;
                    o[nj][2 * r + 1] *= alpha;
                }
                float psum = 0.f;
                #pragma unroll
                for (int nj = 0; nj < 8; nj++) {
                    const float p0 = exp2f(sacc[nj][2 * r] - mnew);
                    const float p1 = exp2f(sacc[nj][2 * r + 1] - mnew);
                    sacc[nj][2 * r] = p0;
                    sacc[nj][2 * r + 1] = p1;
                    psum += p0 + p1;
                }
                lr[r] += psum;
            }

            uint32_t ap[4][4];
            #pragma unroll
            for (int kp = 0; kp < 4; kp++) {
                const int nj = 2 * kp;
                __half2 t0 = __float22half2_rn(make_float2(sacc[nj][0], sacc[nj][1]));
                __half2 t1 = __float22half2_rn(make_float2(sacc[nj][2], sacc[nj][3]));
                __half2 t2 = __float22half2_rn(make_float2(sacc[nj + 1][0], sacc[nj + 1][1]));
                __half2 t3 = __float22half2_rn(make_float2(sacc[nj + 1][2], sacc[nj + 1][3]));
                ap[kp][0] = *(uint32_t*)&t0;
                ap[kp][1] = *(uint32_t*)&t1;
                ap[kp][2] = *(uint32_t*)&t2;
                ap[kp][3] = *(uint32_t*)&t3;
            }

            #pragma unroll
            for (int kp = 0; kp < 4; kp++) {
                uint32_t bv[4][4];
                #pragma unroll
                for (int pd = 0; pd < 4; pd++) {
                    const int row = kp * 16 + (lane & 7) + ((lane >> 4) << 3);
                    const int col = pd * 16 + (((lane >> 3) & 1) << 3);
                    ldsm4t(bv[pd], sV + (uint32_t)(row * SV + col) * 2);
                }
                #pragma unroll
                for (int pd = 0; pd < 4; pd++) {
                    mma_f16(o[2 * pd],     ap[kp], bv[pd][0], bv[pd][2]);
                    mma_f16(o[2 * pd + 1], ap[kp], bv[pd][1], bv[pd][3]);
                }
            }
        }
        __syncthreads();
    }

    float inv[2];
    #pragma unroll
    for (int r = 0; r < 2; r++) {
        float ls = lr[r];
        ls += __shfl_xor_sync(0xFFFFFFFFu, ls, 1);
        ls += __shfl_xor_sync(0xFFFFFFFFu, ls, 2);
        inv[r] = 1.0f / ls;
    }
    #pragma unroll
    for (int r = 0; r < 2; r++) {
        const int trow = qt * AQT + wid * 16 + (lane >> 2) + 8 * r;
        const size_t rowoff = (size_t)(b * SEQT + trow) * EMB + h * HDIM;
        #pragma unroll
        for (int nj = 0; nj < 8; nj++) {
            const int col = nj * 8 + 2 * (lane & 3);
            *(__half2*)&outh[rowoff + col] =
                __floats2half2_rn(o[nj][2 * r] * inv[r], o[nj][2 * r + 1] * inv[r]);
        }
    }
}

// ---------------------------------------------------------------------------
// Launch sequence
// ---------------------------------------------------------------------------
extern "C" void kernel_launch(void* const* d_in, const int* in_sizes, int n_in,
                              void* d_out, int out_size)
{
    const float* x  = (const float*)d_in[0];
    const float* W1 = (const float*)d_in[1];
    const float* W2 = (const float*)d_in[2];
    float* out = (float*)d_out;

    void *p_x16, *p_w1, *p_w2, *p_ah, *p_qh, *p_kh, *p_vh;
    cudaGetSymbolAddress(&p_x16, g_x16);
    cudaGetSymbolAddress(&p_w1, g_w1); cudaGetSymbolAddress(&p_w2, g_w2);
    cudaGetSymbolAddress(&p_ah, g_ah);
    cudaGetSymbolAddress(&p_qh, g_qh); cudaGetSymbolAddress(&p_kh, g_kh);
    cudaGetSymbolAddress(&p_vh, g_vh);

    cudaFuncSetAttribute(gemm_f16<0>, cudaFuncAttributeMaxDynamicSharedMemorySize, GEMM_SMEM);
    cudaFuncSetAttribute(gemm_f16<2>, cudaFuncAttributeMaxDynamicSharedMemorySize, GEMM_SMEM);
    cudaFuncSetAttribute(attn_mma,    cudaFuncAttributeMaxDynamicSharedMemorySize, ATTN_SMEM);

    // one merged conversion launch
    convert_all<<<(ALLN4 + 255) / 256, 256>>>(
        x, W1, W2, (__half*)p_x16, (__half*)p_w1, (__half*)p_w2);

    // qkv = x @ W1^T with fused RoPE + repack epilogue (persistent tiles)
    {
        const int tiles = (MROWS / GBM) * (E3 / GBN);   // 768
        const int grid = tiles < PGRID ? tiles : PGRID;
        gemm_f16<2><<<grid, 256, GEMM_SMEM>>>(
            (const __half*)p_x16, (const __half*)p_w1, nullptr, E3, tiles,
            (__half*)p_qh, (__half*)p_kh, (__half*)p_vh);
    }

    // attention -> fp16
    {
        dim3 ga(SEQT / AQT, BATCH * NHEAD);
        attn_mma<<<ga, 256, ATTN_SMEM>>>((const __half*)p_qh, (const __half*)p_kh,
                                         (const __half*)p_vh, (__half*)p_ah);
    }

    // out = att @ W2^T  (fp32 out, single pass, persistent tiles)
    {
        const int tiles = (MROWS / GBM) * (EMB / GBN);  // 256
        const int grid = tiles < PGRID ? tiles : PGRID;
        gemm_f16<0><<<grid, 256, GEMM_SMEM>>>(
            (const __half*)p_ah, (const __half*)p_w2, out, EMB, tiles,
            nullptr, nullptr, nullptr);
    }
}